// round 1
// baseline (speedup 1.0000x reference)
#include <cuda_runtime.h>
#include <math.h>

// Problem constants (fixed shapes for this problem instance)
#define T_TOK 8192      // B*S tokens
#define D_DIM 1024
#define E_NUM 8
#define H_DIM 512
#define TOPK  2

// ---------------- device scratch (no cudaMalloc allowed) ----------------
__device__ int   g_count[E_NUM];
__device__ int   g_entry[E_NUM][T_TOK];   // entry = token*2 + slot (slot 0 = top1, 1 = top2)
__device__ float g_gateW[E_NUM][T_TOK];   // softmax prob for that (token, expert)
__device__ __align__(16) float g_U[(size_t)2 * T_TOK * H_DIM];  // SwiGLU hidden per (token,slot)
__device__ __align__(16) float g_Y[(size_t)2 * T_TOK * D_DIM];  // gated down-proj per (token,slot)

// ---------------- kernel 0: zero per-expert counters --------------------
__global__ void zero_counts_kernel() {
    if (threadIdx.x < E_NUM) g_count[threadIdx.x] = 0;
}

// ---------------- kernel 1: router (logits -> softmax -> top2) ----------
// One warp per token. w_router staged in smem (32 KB).
__global__ void router_kernel(const float* __restrict__ x,
                              const float* __restrict__ wr) {
    __shared__ float sWr[D_DIM * E_NUM];
    for (int i = threadIdx.x; i < D_DIM * E_NUM; i += blockDim.x) sWr[i] = wr[i];
    __syncthreads();

    int warp = threadIdx.x >> 5;
    int lane = threadIdx.x & 31;
    int t = blockIdx.x * 8 + warp;
    if (t >= T_TOK) return;

    float acc[E_NUM];
#pragma unroll
    for (int e = 0; e < E_NUM; e++) acc[e] = 0.f;

    const float* xr = x + (size_t)t * D_DIM;
    for (int d = lane; d < D_DIM; d += 32) {
        float xv = xr[d];
#pragma unroll
        for (int e = 0; e < E_NUM; e++)
            acc[e] = fmaf(xv, sWr[d * E_NUM + e], acc[e]);
    }
#pragma unroll
    for (int off = 16; off > 0; off >>= 1) {
#pragma unroll
        for (int e = 0; e < E_NUM; e++)
            acc[e] += __shfl_down_sync(0xffffffffu, acc[e], off);
    }

    if (lane == 0) {
        float m = acc[0];
#pragma unroll
        for (int e = 1; e < E_NUM; e++) m = fmaxf(m, acc[e]);
        float p[E_NUM], s = 0.f;
#pragma unroll
        for (int e = 0; e < E_NUM; e++) { p[e] = expf(acc[e] - m); s += p[e]; }
        float inv = 1.f / s;
#pragma unroll
        for (int e = 0; e < E_NUM; e++) p[e] *= inv;

        // top-1 (strict > keeps lowest index on ties, matching lax.top_k)
        int e0 = 0;
#pragma unroll
        for (int e = 1; e < E_NUM; e++) if (p[e] > p[e0]) e0 = e;
        // top-2
        int e1 = (e0 == 0) ? 1 : 0;
#pragma unroll
        for (int e = 0; e < E_NUM; e++) {
            if (e == e0) continue;
            if (p[e] > p[e1]) e1 = e;
        }

        int pos0 = atomicAdd(&g_count[e0], 1);
        g_entry[e0][pos0] = t * 2 + 0;
        g_gateW[e0][pos0] = p[e0];
        int pos1 = atomicAdd(&g_count[e1], 1);
        g_entry[e1][pos1] = t * 2 + 1;
        g_gateW[e1][pos1] = p[e1];
    }
}

// ---------------- kernel 2: grouped up-proj + fused SwiGLU --------------
// For each expert e: U = silu(Xg @ W1_e) * (Xg @ W3_e), rows gathered by list.
// Tiles: BM=64 tokens x BN=64 hidden, BK=16. Shares the A-tile for both GEMMs.
#define BM 64
#define BN 64
#define BK 16

__global__ __launch_bounds__(256) void expert_up_kernel(const float* __restrict__ x,
                                                        const float* __restrict__ w1,
                                                        const float* __restrict__ w3) {
    const int e = blockIdx.z;
    const int count = g_count[e];
    const int m0 = blockIdx.x * BM;
    if (m0 >= count) return;
    const int n0 = blockIdx.y * BN;

    __shared__ __align__(16) float As[BK][BM];
    __shared__ __align__(16) float B1s[BK][BN];
    __shared__ __align__(16) float B3s[BK][BN];
    __shared__ int sEnt[BM];
    __shared__ int sTok[BM];

    const int tid = threadIdx.x;
    if (tid < BM) {
        int p = m0 + tid;
        int ent = (p < count) ? g_entry[e][p] : 0;
        sEnt[tid] = (p < count) ? ent : -1;
        sTok[tid] = ent >> 1;
    }
    __syncthreads();

    const float* W1 = w1 + (size_t)e * D_DIM * H_DIM;
    const float* W3 = w3 + (size_t)e * D_DIM * H_DIM;

    const int tx = tid & 15;   // n-group (4 cols)
    const int ty = tid >> 4;   // m-group (4 rows)
    float acc1[4][4] = {};
    float acc3[4][4] = {};

    const int arow = tid >> 2, aq = tid & 3;   // A loads: 64 rows x 4 float4
    const int bk = tid >> 4, bn = tid & 15;    // B loads: 16 k-rows x 16 float4

    const float* xrow = x + (size_t)sTok[arow] * D_DIM + aq * 4;

    for (int k0 = 0; k0 < D_DIM; k0 += BK) {
        float4 av = *(const float4*)(xrow + k0);
        As[aq * 4 + 0][arow] = av.x;
        As[aq * 4 + 1][arow] = av.y;
        As[aq * 4 + 2][arow] = av.z;
        As[aq * 4 + 3][arow] = av.w;

        const float4 b1v = *(const float4*)(W1 + (size_t)(k0 + bk) * H_DIM + n0 + bn * 4);
        const float4 b3v = *(const float4*)(W3 + (size_t)(k0 + bk) * H_DIM + n0 + bn * 4);
        *(float4*)&B1s[bk][bn * 4] = b1v;
        *(float4*)&B3s[bk][bn * 4] = b3v;
        __syncthreads();

#pragma unroll
        for (int kk = 0; kk < BK; kk++) {
            float4 a  = *(const float4*)&As[kk][ty * 4];
            float4 b1 = *(const float4*)&B1s[kk][tx * 4];
            float4 b3 = *(const float4*)&B3s[kk][tx * 4];
            float am[4] = {a.x, a.y, a.z, a.w};
            float v1[4] = {b1.x, b1.y, b1.z, b1.w};
            float v3[4] = {b3.x, b3.y, b3.z, b3.w};
#pragma unroll
            for (int i = 0; i < 4; i++) {
#pragma unroll
                for (int j = 0; j < 4; j++) {
                    acc1[i][j] = fmaf(am[i], v1[j], acc1[i][j]);
                    acc3[i][j] = fmaf(am[i], v3[j], acc3[i][j]);
                }
            }
        }
        __syncthreads();
    }

#pragma unroll
    for (int i = 0; i < 4; i++) {
        int p = m0 + ty * 4 + i;
        if (p < count) {
            int ent = sEnt[ty * 4 + i];
            float* urow = g_U + (size_t)ent * H_DIM + n0 + tx * 4;
#pragma unroll
            for (int j = 0; j < 4; j++) {
                float z = acc1[i][j];
                float sig = 1.f / (1.f + expf(-z));
                urow[j] = z * sig * acc3[i][j];
            }
        }
    }
}

// ---------------- kernel 3: grouped down-proj with gate in epilogue -----
// For each expert e: Yc = U_e @ W2_e (K=512, N=1024), Y[entry] = gate * Yc.
__global__ __launch_bounds__(256) void expert_down_kernel(const float* __restrict__ w2) {
    const int e = blockIdx.z;
    const int count = g_count[e];
    const int m0 = blockIdx.x * BM;
    if (m0 >= count) return;
    const int n0 = blockIdx.y * BN;

    __shared__ __align__(16) float As[BK][BM];
    __shared__ __align__(16) float Bs[BK][BN];
    __shared__ int   sEnt[BM];
    __shared__ float sGate[BM];

    const int tid = threadIdx.x;
    if (tid < BM) {
        int p = m0 + tid;
        int ent = (p < count) ? g_entry[e][p] : 0;
        sEnt[tid] = (p < count) ? ent : -1;
        sGate[tid] = (p < count) ? g_gateW[e][p] : 0.f;
    }
    __syncthreads();

    const float* W2 = w2 + (size_t)e * H_DIM * D_DIM;

    const int tx = tid & 15;
    const int ty = tid >> 4;
    float acc[4][4] = {};

    const int arow = tid >> 2, aq = tid & 3;
    const int bk = tid >> 4, bn = tid & 15;

    const int entA = (sEnt[arow] >= 0) ? sEnt[arow] : 0;
    const float* urow = g_U + (size_t)entA * H_DIM + aq * 4;

    for (int k0 = 0; k0 < H_DIM; k0 += BK) {
        float4 av = *(const float4*)(urow + k0);
        As[aq * 4 + 0][arow] = av.x;
        As[aq * 4 + 1][arow] = av.y;
        As[aq * 4 + 2][arow] = av.z;
        As[aq * 4 + 3][arow] = av.w;

        const float4 bv = *(const float4*)(W2 + (size_t)(k0 + bk) * D_DIM + n0 + bn * 4);
        *(float4*)&Bs[bk][bn * 4] = bv;
        __syncthreads();

#pragma unroll
        for (int kk = 0; kk < BK; kk++) {
            float4 a = *(const float4*)&As[kk][ty * 4];
            float4 b = *(const float4*)&Bs[kk][tx * 4];
            float am[4] = {a.x, a.y, a.z, a.w};
            float bb[4] = {b.x, b.y, b.z, b.w};
#pragma unroll
            for (int i = 0; i < 4; i++) {
#pragma unroll
                for (int j = 0; j < 4; j++) {
                    acc[i][j] = fmaf(am[i], bb[j], acc[i][j]);
                }
            }
        }
        __syncthreads();
    }

#pragma unroll
    for (int i = 0; i < 4; i++) {
        int p = m0 + ty * 4 + i;
        if (p < count) {
            int ent = sEnt[ty * 4 + i];
            float g = sGate[ty * 4 + i];
            float* yrow = g_Y + (size_t)ent * D_DIM + n0 + tx * 4;
#pragma unroll
            for (int j = 0; j < 4; j++) yrow[j] = g * acc[i][j];
        }
    }
}

// ---------------- kernel 4: combine the two slots per token -------------
__global__ void combine_kernel(float* __restrict__ out) {
    size_t idx4 = (size_t)blockIdx.x * blockDim.x + threadIdx.x;
    size_t total4 = (size_t)T_TOK * D_DIM / 4;
    if (idx4 >= total4) return;
    size_t base = idx4 * 4;
    size_t t = base >> 10;          // / D_DIM
    size_t d = base & (D_DIM - 1);
    float4 a = *(const float4*)(g_Y + ((size_t)(2 * t) * D_DIM + d));
    float4 b = *(const float4*)(g_Y + ((size_t)(2 * t + 1) * D_DIM + d));
    float4 r;
    r.x = a.x + b.x; r.y = a.y + b.y; r.z = a.z + b.z; r.w = a.w + b.w;
    *(float4*)(out + base) = r;
}

// ---------------- launch ----------------
extern "C" void kernel_launch(void* const* d_in, const int* in_sizes, int n_in,
                              void* d_out, int out_size) {
    const float* x  = (const float*)d_in[0];
    const float* wr = (const float*)d_in[1];
    const float* w1 = (const float*)d_in[2];
    const float* w2 = (const float*)d_in[3];
    const float* w3 = (const float*)d_in[4];
    // d_in[5] = top_k (hardcoded 2)
    float* out = (float*)d_out;

    zero_counts_kernel<<<1, 32>>>();
    router_kernel<<<T_TOK / 8, 256>>>(x, wr);

    dim3 gUp(T_TOK / BM, H_DIM / BN, E_NUM);     // (128, 8, 8); tiles past count exit early
    expert_up_kernel<<<gUp, 256>>>(x, w1, w3);

    dim3 gDown(T_TOK / BM, D_DIM / BN, E_NUM);   // (128, 16, 8)
    expert_down_kernel<<<gDown, 256>>>(w2);

    size_t total4 = (size_t)T_TOK * D_DIM / 4;
    combine_kernel<<<(unsigned)((total4 + 255) / 256), 256>>>(out);
}

// round 4
// speedup vs baseline: 2.6929x; 2.6929x over previous
#include <cuda_runtime.h>
#include <cstdint>
#include <math.h>

// ---------------- problem constants ----------------
#define T_TOK 8192
#define D_DIM 1024
#define E_NUM 8
#define H_DIM 512
#define NSLOT (2 * T_TOK)

// ---------------- device scratch (referenced ONLY from device code) ------
__device__ int   g_count[E_NUM];
__device__ int   g_entry[E_NUM][T_TOK];
__device__ float g_gateW[E_NUM][T_TOK];
__device__ __align__(16) float g_Xr[(size_t)T_TOK * D_DIM];           // tf32-rounded x
__device__ __align__(16) float g_w1r[(size_t)E_NUM * D_DIM * H_DIM];  // [e][d][h] rounded
__device__ __align__(16) float g_w3r[(size_t)E_NUM * D_DIM * H_DIM];
__device__ __align__(16) float g_w2r[(size_t)E_NUM * H_DIM * D_DIM];  // [e][h][d] rounded
__device__ __align__(16) float g_U[(size_t)NSLOT * H_DIM];            // SwiGLU hidden (rounded)
__device__ __align__(16) float g_Y[(size_t)NSLOT * D_DIM];            // gated down-proj

// ---------------- helpers (sm_80-level PTX only) ----
__device__ __forceinline__ uint32_t smem_u32(const void* p) {
    uint32_t a;
    asm("{ .reg .u64 t; cvta.to.shared.u64 t, %1; cvt.u32.u64 %0, t; }" : "=r"(a) : "l"(p));
    return a;
}
__device__ __forceinline__ float tf32r(float v) {
    uint32_t u;
    asm("cvt.rna.tf32.f32 %0, %1;" : "=r"(u) : "f"(v));
    return __uint_as_float(u);
}
__device__ __forceinline__ void cp16(uint32_t dst, const void* src) {
    asm volatile("cp.async.cg.shared.global [%0], [%1], 16;" :: "r"(dst), "l"(src));
}
#define CP_COMMIT() asm volatile("cp.async.commit_group;" ::: "memory")
#define CP_WAIT1()  asm volatile("cp.async.wait_group 1;" ::: "memory")

// mma.sync m16n8k8 tf32: D = A*B + D
__device__ __forceinline__ void mma8(float* c, const uint32_t* a, const uint32_t* b) {
    asm volatile(
        "mma.sync.aligned.m16n8k8.row.col.f32.tf32.tf32.f32 "
        "{%0,%1,%2,%3}, {%4,%5,%6,%7}, {%8,%9}, {%0,%1,%2,%3};"
        : "+f"(c[0]), "+f"(c[1]), "+f"(c[2]), "+f"(c[3])
        : "r"(a[0]), "r"(a[1]), "r"(a[2]), "r"(a[3]), "r"(b[0]), "r"(b[1]));
}

// ---------------- kernel: zero counters ----------------
__global__ void zero_counts_kernel() {
    if (threadIdx.x < E_NUM) g_count[threadIdx.x] = 0;
}

// ---------------- kernel: router (fp32, verified in R1) ----------------
__global__ void router_kernel(const float* __restrict__ x, const float* __restrict__ wr) {
    __shared__ float sWr[D_DIM * E_NUM];
    for (int i = threadIdx.x; i < D_DIM * E_NUM; i += blockDim.x) sWr[i] = wr[i];
    __syncthreads();

    int warp = threadIdx.x >> 5, lane = threadIdx.x & 31;
    int t = blockIdx.x * 8 + warp;
    if (t >= T_TOK) return;

    float acc[E_NUM];
#pragma unroll
    for (int e = 0; e < E_NUM; e++) acc[e] = 0.f;
    const float* xr = x + (size_t)t * D_DIM;
    for (int d = lane; d < D_DIM; d += 32) {
        float xv = xr[d];
#pragma unroll
        for (int e = 0; e < E_NUM; e++) acc[e] = fmaf(xv, sWr[d * E_NUM + e], acc[e]);
    }
#pragma unroll
    for (int off = 16; off > 0; off >>= 1)
#pragma unroll
        for (int e = 0; e < E_NUM; e++) acc[e] += __shfl_down_sync(0xffffffffu, acc[e], off);

    if (lane == 0) {
        float m = acc[0];
#pragma unroll
        for (int e = 1; e < E_NUM; e++) m = fmaxf(m, acc[e]);
        float p[E_NUM], s = 0.f;
#pragma unroll
        for (int e = 0; e < E_NUM; e++) { p[e] = expf(acc[e] - m); s += p[e]; }
        float inv = 1.f / s;
#pragma unroll
        for (int e = 0; e < E_NUM; e++) p[e] *= inv;

        int e0 = 0;
#pragma unroll
        for (int e = 1; e < E_NUM; e++) if (p[e] > p[e0]) e0 = e;
        int e1 = (e0 == 0) ? 1 : 0;
#pragma unroll
        for (int e = 0; e < E_NUM; e++) {
            if (e == e0) continue;
            if (p[e] > p[e1]) e1 = e;
        }
        int pos0 = atomicAdd(&g_count[e0], 1);
        g_entry[e0][pos0] = t * 2 + 0;
        g_gateW[e0][pos0] = p[e0];
        int pos1 = atomicAdd(&g_count[e1], 1);
        g_entry[e1][pos1] = t * 2 + 1;
        g_gateW[e1][pos1] = p[e1];
    }
}

// ---------------- kernel: round x -> g_Xr (symbol referenced on device) --
__global__ void round_x_kernel(const float* __restrict__ x) {
    size_t i4 = (size_t)blockIdx.x * blockDim.x + threadIdx.x;
    if (i4 >= (size_t)T_TOK * D_DIM / 4) return;
    float4 v = *(const float4*)(x + i4 * 4);
    v.x = tf32r(v.x); v.y = tf32r(v.y); v.z = tf32r(v.z); v.w = tf32r(v.w);
    *(float4*)(g_Xr + i4 * 4) = v;
}

// ---------------- kernel: round weights -> g_w{1,3,2}r ------------------
__global__ void round_w_kernel(const float* __restrict__ w1,
                               const float* __restrict__ w2,
                               const float* __restrict__ w3) {
    size_t i4 = (size_t)blockIdx.x * blockDim.x + threadIdx.x;
    size_t n4 = (size_t)E_NUM * D_DIM * H_DIM / 4;
    if (i4 >= n4) return;
    float4 a = *(const float4*)(w1 + i4 * 4);
    a.x = tf32r(a.x); a.y = tf32r(a.y); a.z = tf32r(a.z); a.w = tf32r(a.w);
    *(float4*)(g_w1r + i4 * 4) = a;
    float4 b = *(const float4*)(w3 + i4 * 4);
    b.x = tf32r(b.x); b.y = tf32r(b.y); b.z = tf32r(b.z); b.w = tf32r(b.w);
    *(float4*)(g_w3r + i4 * 4) = b;
    float4 c = *(const float4*)(w2 + i4 * 4);
    c.x = tf32r(c.x); c.y = tf32r(c.y); c.z = tf32r(c.z); c.w = tf32r(c.w);
    *(float4*)(g_w2r + i4 * 4) = c;
}

// ---------------- GEMM tiling constants ----------------
#define BKT 32                       // K per smem tile
#define A_STR_F 36                   // A smem row stride (floats)
#define A_TILE_B (128 * A_STR_F * 4) // 18432 B
#define BU_STR_F 72                  // up B smem row stride (floats)
#define BU_TILE_B (BKT * BU_STR_F * 4)  // 9216 B
#define BD_STR_F 136                 // down B smem row stride (floats)
#define BD_TILE_B (BKT * BD_STR_F * 4)  // 17408 B

// ============================================================
// UP: per expert, U = silu(Xg@W1)*(Xg@W3). CTA: M=128, N=64 (each of w1,w3), K=1024.
// 8 warps in 4(m)x2(n): warp tile 32m x 32n per GEMM.
// ============================================================
__global__ __launch_bounds__(256, 1) void up_gemm_kernel() {
    const int e = blockIdx.z;
    const int count = g_count[e];
    const int m0 = blockIdx.x * 128;
    if (m0 >= count) return;
    const int n0 = blockIdx.y * 64;

    extern __shared__ __align__(128) char smem[];
    __shared__ int sTok[128];
    __shared__ int sEnt[128];

    const int tid = threadIdx.x;
    const int wid = tid >> 5, lane = tid & 31;
    const int warp_m = wid >> 1, warp_n = wid & 1;

    uint32_t base = smem_u32(smem);
    uint32_t aB[2]  = { base,                 base + A_TILE_B };
    uint32_t b1B[2] = { base + 2*A_TILE_B,            base + 2*A_TILE_B + BU_TILE_B };
    uint32_t b3B[2] = { base + 2*A_TILE_B + 2*BU_TILE_B, base + 2*A_TILE_B + 3*BU_TILE_B };

    if (tid < 128) {
        int p = m0 + tid;
        int ent = (p < count) ? g_entry[e][p] : g_entry[e][0];
        sEnt[tid] = ent;
        sTok[tid] = ent >> 1;
    }
    __syncthreads();

    const float* W1 = g_w1r + (size_t)e * D_DIM * H_DIM;
    const float* W3 = g_w3r + (size_t)e * D_DIM * H_DIM;

    auto load_tile = [&](int buf, int k0) {
#pragma unroll
        for (int i = 0; i < 4; i++) {            // A: 128 rows x 8 chunks
            int c = tid + i * 256, row = c >> 3, q = c & 7;
            cp16(aB[buf] + row * (A_STR_F * 4) + q * 16,
                 g_Xr + (size_t)sTok[row] * D_DIM + k0 + q * 4);
        }
#pragma unroll
        for (int i = 0; i < 2; i++) {            // B1: 32 k-rows x 16 chunks
            int c = tid + i * 256, kr = c >> 4, q = c & 15;
            cp16(b1B[buf] + kr * (BU_STR_F * 4) + q * 16,
                 W1 + (size_t)(k0 + kr) * H_DIM + n0 + q * 4);
        }
#pragma unroll
        for (int i = 0; i < 2; i++) {            // B3
            int c = tid + i * 256, kr = c >> 4, q = c & 15;
            cp16(b3B[buf] + kr * (BU_STR_F * 4) + q * 16,
                 W3 + (size_t)(k0 + kr) * H_DIM + n0 + q * 4);
        }
        CP_COMMIT();
    };

    load_tile(0, 0);
    load_tile(1, BKT);

    float acc1[2][4][4] = {};
    float acc3[2][4][4] = {};

    const int lrow = lane >> 2;      // groupID 0..7
    const int lcol = lane & 3;       // tig 0..3
    const int NT = D_DIM / BKT;      // 32

    for (int kt = 0; kt < NT; kt++) {
        const int cur = kt & 1;
        CP_WAIT1();
        __syncthreads();

        const char* aP  = (const char*)smem + (aB[cur]  - base);
        const char* b1P = (const char*)smem + (b1B[cur] - base);
        const char* b3P = (const char*)smem + (b3B[cur] - base);

#pragma unroll
        for (int ks = 0; ks < BKT / 8; ks++) {
            uint32_t a[2][4], b1[4][2], b3[4][2];
#pragma unroll
            for (int mt = 0; mt < 2; mt++) {
                int m = warp_m * 32 + mt * 16 + lrow;
                int k = ks * 8 + lcol;
                const uint32_t* r0 = (const uint32_t*)(aP + (size_t)m * (A_STR_F * 4));
                const uint32_t* r1 = (const uint32_t*)(aP + (size_t)(m + 8) * (A_STR_F * 4));
                a[mt][0] = r0[k];     a[mt][1] = r1[k];
                a[mt][2] = r0[k + 4]; a[mt][3] = r1[k + 4];
            }
#pragma unroll
            for (int nt = 0; nt < 4; nt++) {
                int n = warp_n * 32 + nt * 8 + lrow;
                int k = ks * 8 + lcol;
                b1[nt][0] = ((const uint32_t*)(b1P + (size_t)k * (BU_STR_F * 4)))[n];
                b1[nt][1] = ((const uint32_t*)(b1P + (size_t)(k + 4) * (BU_STR_F * 4)))[n];
                b3[nt][0] = ((const uint32_t*)(b3P + (size_t)k * (BU_STR_F * 4)))[n];
                b3[nt][1] = ((const uint32_t*)(b3P + (size_t)(k + 4) * (BU_STR_F * 4)))[n];
            }
#pragma unroll
            for (int mt = 0; mt < 2; mt++)
#pragma unroll
                for (int nt = 0; nt < 4; nt++) {
                    mma8(acc1[mt][nt], a[mt], b1[nt]);
                    mma8(acc3[mt][nt], a[mt], b3[nt]);
                }
        }
        __syncthreads();
        if (kt + 2 < NT) load_tile(cur, (kt + 2) * BKT);
        else CP_COMMIT();
    }

    // epilogue: silu(u1)*u3 -> g_U (tf32-rounded for the down GEMM)
#pragma unroll
    for (int mt = 0; mt < 2; mt++) {
#pragma unroll
        for (int half = 0; half < 2; half++) {
            int r = warp_m * 32 + mt * 16 + lrow + half * 8;
            if (m0 + r < count) {
                float* urow = g_U + (size_t)sEnt[r] * H_DIM;
#pragma unroll
                for (int nt = 0; nt < 4; nt++) {
                    int cbase = n0 + warp_n * 32 + nt * 8 + 2 * lcol;
                    float z0 = acc1[mt][nt][half * 2 + 0];
                    float z1 = acc1[mt][nt][half * 2 + 1];
                    float2 o;
                    o.x = tf32r(z0 / (1.f + expf(-z0)) * acc3[mt][nt][half * 2 + 0]);
                    o.y = tf32r(z1 / (1.f + expf(-z1)) * acc3[mt][nt][half * 2 + 1]);
                    *(float2*)(urow + cbase) = o;
                }
            }
        }
    }
}

// ============================================================
// DOWN: per expert, Y = gate * (U@W2). CTA: M=128, N=128, K=512.
// 8 warps in 4(m)x2(n): warp tile 32m x 64n.
// ============================================================
__global__ __launch_bounds__(256, 1) void down_gemm_kernel() {
    const int e = blockIdx.z;
    const int count = g_count[e];
    const int m0 = blockIdx.x * 128;
    if (m0 >= count) return;
    const int n0 = blockIdx.y * 128;

    extern __shared__ __align__(128) char smem[];
    __shared__ int   sEnt[128];
    __shared__ float sGate[128];

    const int tid = threadIdx.x;
    const int wid = tid >> 5, lane = tid & 31;
    const int warp_m = wid >> 1, warp_n = wid & 1;

    uint32_t base = smem_u32(smem);
    uint32_t aB[2] = { base,              base + A_TILE_B };
    uint32_t bB[2] = { base + 2*A_TILE_B, base + 2*A_TILE_B + BD_TILE_B };

    if (tid < 128) {
        int p = m0 + tid;
        sEnt[tid]  = (p < count) ? g_entry[e][p] : g_entry[e][0];
        sGate[tid] = (p < count) ? g_gateW[e][p] : 0.f;
    }
    __syncthreads();

    const float* W2 = g_w2r + (size_t)e * H_DIM * D_DIM;

    auto load_tile = [&](int buf, int k0) {
#pragma unroll
        for (int i = 0; i < 4; i++) {            // A: 128 rows x 8 chunks
            int c = tid + i * 256, row = c >> 3, q = c & 7;
            cp16(aB[buf] + row * (A_STR_F * 4) + q * 16,
                 g_U + (size_t)sEnt[row] * H_DIM + k0 + q * 4);
        }
#pragma unroll
        for (int i = 0; i < 4; i++) {            // B: 32 k-rows x 32 chunks
            int c = tid + i * 256, kr = c >> 5, q = c & 31;
            cp16(bB[buf] + kr * (BD_STR_F * 4) + q * 16,
                 W2 + (size_t)(k0 + kr) * D_DIM + n0 + q * 4);
        }
        CP_COMMIT();
    };

    load_tile(0, 0);
    load_tile(1, BKT);

    float acc[2][8][4] = {};

    const int lrow = lane >> 2;
    const int lcol = lane & 3;
    const int NT = H_DIM / BKT;   // 16

    for (int kt = 0; kt < NT; kt++) {
        const int cur = kt & 1;
        CP_WAIT1();
        __syncthreads();

        const char* aP = (const char*)smem + (aB[cur] - base);
        const char* bP = (const char*)smem + (bB[cur] - base);

#pragma unroll
        for (int ks = 0; ks < BKT / 8; ks++) {
            uint32_t a[2][4], b[8][2];
#pragma unroll
            for (int mt = 0; mt < 2; mt++) {
                int m = warp_m * 32 + mt * 16 + lrow;
                int k = ks * 8 + lcol;
                const uint32_t* r0 = (const uint32_t*)(aP + (size_t)m * (A_STR_F * 4));
                const uint32_t* r1 = (const uint32_t*)(aP + (size_t)(m + 8) * (A_STR_F * 4));
                a[mt][0] = r0[k];     a[mt][1] = r1[k];
                a[mt][2] = r0[k + 4]; a[mt][3] = r1[k + 4];
            }
#pragma unroll
            for (int nt = 0; nt < 8; nt++) {
                int n = warp_n * 64 + nt * 8 + lrow;
                int k = ks * 8 + lcol;
                b[nt][0] = ((const uint32_t*)(bP + (size_t)k * (BD_STR_F * 4)))[n];
                b[nt][1] = ((const uint32_t*)(bP + (size_t)(k + 4) * (BD_STR_F * 4)))[n];
            }
#pragma unroll
            for (int mt = 0; mt < 2; mt++)
#pragma unroll
                for (int nt = 0; nt < 8; nt++)
                    mma8(acc[mt][nt], a[mt], b[nt]);
        }
        __syncthreads();
        if (kt + 2 < NT) load_tile(cur, (kt + 2) * BKT);
        else CP_COMMIT();
    }

#pragma unroll
    for (int mt = 0; mt < 2; mt++) {
#pragma unroll
        for (int half = 0; half < 2; half++) {
            int r = warp_m * 32 + mt * 16 + lrow + half * 8;
            if (m0 + r < count) {
                float g = sGate[r];
                float* yrow = g_Y + (size_t)sEnt[r] * D_DIM;
#pragma unroll
                for (int nt = 0; nt < 8; nt++) {
                    int cbase = n0 + warp_n * 64 + nt * 8 + 2 * lcol;
                    float2 o;
                    o.x = g * acc[mt][nt][half * 2 + 0];
                    o.y = g * acc[mt][nt][half * 2 + 1];
                    *(float2*)(yrow + cbase) = o;
                }
            }
        }
    }
}

// ---------------- kernel: combine two slots per token ----------------
__global__ void combine_kernel(float* __restrict__ out) {
    size_t idx4 = (size_t)blockIdx.x * blockDim.x + threadIdx.x;
    size_t total4 = (size_t)T_TOK * D_DIM / 4;
    if (idx4 >= total4) return;
    size_t bofs = idx4 * 4;
    size_t t = bofs >> 10;
    size_t d = bofs & (D_DIM - 1);
    float4 a = *(const float4*)(g_Y + ((size_t)(2 * t) * D_DIM + d));
    float4 b = *(const float4*)(g_Y + ((size_t)(2 * t + 1) * D_DIM + d));
    float4 r;
    r.x = a.x + b.x; r.y = a.y + b.y; r.z = a.z + b.z; r.w = a.w + b.w;
    *(float4*)(out + bofs) = r;
}

// ---------------- launch ----------------
extern "C" void kernel_launch(void* const* d_in, const int* in_sizes, int n_in,
                              void* d_out, int out_size) {
    const float* x  = (const float*)d_in[0];
    const float* wr = (const float*)d_in[1];
    const float* w1 = (const float*)d_in[2];
    const float* w2 = (const float*)d_in[3];
    const float* w3 = (const float*)d_in[4];
    float* out = (float*)d_out;

    const int UP_SMEM   = 2 * A_TILE_B + 4 * BU_TILE_B;   // 73728
    const int DOWN_SMEM = 2 * A_TILE_B + 2 * BD_TILE_B;   // 71680

    cudaFuncSetAttribute(up_gemm_kernel,   cudaFuncAttributeMaxDynamicSharedMemorySize, UP_SMEM);
    cudaFuncSetAttribute(down_gemm_kernel, cudaFuncAttributeMaxDynamicSharedMemorySize, DOWN_SMEM);

    zero_counts_kernel<<<1, 32>>>();
    router_kernel<<<T_TOK / 8, 256>>>(x, wr);

    // tf32 round-copies into device globals (globals referenced ONLY in device code)
    round_x_kernel<<<(T_TOK * D_DIM / 4 + 255) / 256, 256>>>(x);
    {
        int n4 = E_NUM * D_DIM * H_DIM / 4;   // 1M float4 per weight tensor
        round_w_kernel<<<(n4 + 255) / 256, 256>>>(w1, w2, w3);
    }

    {
        dim3 g(T_TOK / 128, H_DIM / 64, E_NUM);   // (64, 8, 8)
        up_gemm_kernel<<<g, 256, UP_SMEM>>>();
    }
    {
        dim3 g(T_TOK / 128, D_DIM / 128, E_NUM);  // (64, 8, 8)
        down_gemm_kernel<<<g, 256, DOWN_SMEM>>>();
    }

    size_t total4 = (size_t)T_TOK * D_DIM / 4;
    combine_kernel<<<(unsigned)((total4 + 255) / 256), 256>>>(out);
}

// round 5
// speedup vs baseline: 3.0163x; 1.1201x over previous
#include <cuda_runtime.h>
#include <cstdint>
#include <math.h>

// ---------------- problem constants ----------------
#define T_TOK 8192
#define D_DIM 1024
#define E_NUM 8
#define H_DIM 512
#define NSLOT (2 * T_TOK)

// ---------------- device scratch (referenced ONLY from device code) ------
__device__ int   g_count[E_NUM];
__device__ int   g_entry[E_NUM][T_TOK];
__device__ float g_gateW[E_NUM][T_TOK];
__device__ __align__(16) float g_Xr[(size_t)T_TOK * D_DIM];   // tf32-rounded x
__device__ __align__(16) float g_U[(size_t)NSLOT * H_DIM];    // SwiGLU hidden (rounded)
__device__ __align__(16) float g_Y[(size_t)NSLOT * D_DIM];    // gated down-proj

// ---------------- helpers (sm_80-level PTX only) ----
__device__ __forceinline__ uint32_t smem_u32(const void* p) {
    uint32_t a;
    asm("{ .reg .u64 t; cvta.to.shared.u64 t, %1; cvt.u32.u64 %0, t; }" : "=r"(a) : "l"(p));
    return a;
}
__device__ __forceinline__ float tf32r(float v) {
    uint32_t u;
    asm("cvt.rna.tf32.f32 %0, %1;" : "=r"(u) : "f"(v));
    return __uint_as_float(u);
}
__device__ __forceinline__ uint32_t tf32u(uint32_t raw) {
    uint32_t u;
    asm("cvt.rna.tf32.f32 %0, %1;" : "=r"(u) : "f"(__uint_as_float(raw)));
    return u;
}
__device__ __forceinline__ void cp16(uint32_t dst, const void* src) {
    asm volatile("cp.async.cg.shared.global [%0], [%1], 16;" :: "r"(dst), "l"(src));
}
#define CP_COMMIT() asm volatile("cp.async.commit_group;" ::: "memory")
#define CP_WAIT1()  asm volatile("cp.async.wait_group 1;" ::: "memory")

// mma.sync m16n8k8 tf32: D = A*B + D
__device__ __forceinline__ void mma8(float* c, const uint32_t* a, const uint32_t* b) {
    asm volatile(
        "mma.sync.aligned.m16n8k8.row.col.f32.tf32.tf32.f32 "
        "{%0,%1,%2,%3}, {%4,%5,%6,%7}, {%8,%9}, {%0,%1,%2,%3};"
        : "+f"(c[0]), "+f"(c[1]), "+f"(c[2]), "+f"(c[3])
        : "r"(a[0]), "r"(a[1]), "r"(a[2]), "r"(a[3]), "r"(b[0]), "r"(b[1]));
}

// ---------------- kernel: zero counters ----------------
__global__ void zero_counts_kernel() {
    if (threadIdx.x < E_NUM) g_count[threadIdx.x] = 0;
}

// ---------------- kernel: router + fused tf32 round of x ----------------
__global__ void router_kernel(const float* __restrict__ x, const float* __restrict__ wr) {
    __shared__ float sWr[D_DIM * E_NUM];
    for (int i = threadIdx.x; i < D_DIM * E_NUM; i += blockDim.x) sWr[i] = wr[i];
    __syncthreads();

    int warp = threadIdx.x >> 5, lane = threadIdx.x & 31;
    int t = blockIdx.x * 8 + warp;
    if (t >= T_TOK) return;

    float acc[E_NUM];
#pragma unroll
    for (int e = 0; e < E_NUM; e++) acc[e] = 0.f;
    const float* xr = x + (size_t)t * D_DIM;
    float* xo = g_Xr + (size_t)t * D_DIM;
    for (int d = lane; d < D_DIM; d += 32) {
        float xv = xr[d];
        xo[d] = tf32r(xv);                          // fused round-copy
#pragma unroll
        for (int e = 0; e < E_NUM; e++) acc[e] = fmaf(xv, sWr[d * E_NUM + e], acc[e]);
    }
#pragma unroll
    for (int off = 16; off > 0; off >>= 1)
#pragma unroll
        for (int e = 0; e < E_NUM; e++) acc[e] += __shfl_down_sync(0xffffffffu, acc[e], off);

    if (lane == 0) {
        float m = acc[0];
#pragma unroll
        for (int e = 1; e < E_NUM; e++) m = fmaxf(m, acc[e]);
        float p[E_NUM], s = 0.f;
#pragma unroll
        for (int e = 0; e < E_NUM; e++) { p[e] = expf(acc[e] - m); s += p[e]; }
        float inv = 1.f / s;
#pragma unroll
        for (int e = 0; e < E_NUM; e++) p[e] *= inv;

        int e0 = 0;
#pragma unroll
        for (int e = 1; e < E_NUM; e++) if (p[e] > p[e0]) e0 = e;
        int e1 = (e0 == 0) ? 1 : 0;
#pragma unroll
        for (int e = 0; e < E_NUM; e++) {
            if (e == e0) continue;
            if (p[e] > p[e1]) e1 = e;
        }
        int pos0 = atomicAdd(&g_count[e0], 1);
        g_entry[e0][pos0] = t * 2 + 0;
        g_gateW[e0][pos0] = p[e0];
        int pos1 = atomicAdd(&g_count[e1], 1);
        g_entry[e1][pos1] = t * 2 + 1;
        g_gateW[e1][pos1] = p[e1];
    }
}

// ---------------- GEMM tiling constants ----------------
#define BKT 32                          // K per smem tile
#define A_STR_F 36                      // A smem row stride (floats)
#define A_TILE_B (128 * A_STR_F * 4)    // 18432 B
#define BU_STR_F 72                     // up B smem row stride (floats)
#define BU_TILE_B (BKT * BU_STR_F * 4)  // 9216 B
#define BD_STR_F 136                    // down B smem row stride (floats)
#define BD_TILE_B (BKT * BD_STR_F * 4)  // 17408 B
#define STAGE_U (A_TILE_B + 2 * BU_TILE_B)  // 36864
#define STAGE_D (A_TILE_B + BD_TILE_B)      // 35840
#define UP_SMEM   (3 * STAGE_U)             // 110592
#define DOWN_SMEM (3 * STAGE_D)             // 107520

// ============================================================
// UP: per expert, U = silu(Xg@W1)*(Xg@W3). CTA: M=128, N=64 (each of w1,w3), K=1024.
// 8 warps in 4(m)x2(n). 3-stage cp.async ring, prefetch before compute.
// Weights read raw; B fragments tf32-rounded in-register.
// ============================================================
__global__ __launch_bounds__(256, 1) void up_gemm_kernel(const float* __restrict__ w1,
                                                         const float* __restrict__ w3) {
    const int e = blockIdx.z;
    const int count = g_count[e];
    const int m0 = blockIdx.x * 128;
    if (m0 >= count) return;
    const int n0 = blockIdx.y * 64;

    extern __shared__ __align__(128) char smem[];
    __shared__ int sTok[128];
    __shared__ int sEnt[128];

    const int tid = threadIdx.x;
    const int wid = tid >> 5, lane = tid & 31;
    const int warp_m = wid >> 1, warp_n = wid & 1;

    uint32_t base = smem_u32(smem);

    if (tid < 128) {
        int p = m0 + tid;
        int ent = (p < count) ? g_entry[e][p] : g_entry[e][0];
        sEnt[tid] = ent;
        sTok[tid] = ent >> 1;
    }
    __syncthreads();

    const float* W1 = w1 + (size_t)e * D_DIM * H_DIM;
    const float* W3 = w3 + (size_t)e * D_DIM * H_DIM;

    auto load_tile = [&](int buf, int k0) {
        uint32_t aB  = base + buf * STAGE_U;
        uint32_t b1B = aB + A_TILE_B;
        uint32_t b3B = b1B + BU_TILE_B;
#pragma unroll
        for (int i = 0; i < 4; i++) {            // A: 128 rows x 8 chunks
            int c = tid + i * 256, row = c >> 3, q = c & 7;
            cp16(aB + row * (A_STR_F * 4) + q * 16,
                 g_Xr + (size_t)sTok[row] * D_DIM + k0 + q * 4);
        }
#pragma unroll
        for (int i = 0; i < 2; i++) {            // B1: 32 k-rows x 16 chunks
            int c = tid + i * 256, kr = c >> 4, q = c & 15;
            cp16(b1B + kr * (BU_STR_F * 4) + q * 16,
                 W1 + (size_t)(k0 + kr) * H_DIM + n0 + q * 4);
        }
#pragma unroll
        for (int i = 0; i < 2; i++) {            // B3
            int c = tid + i * 256, kr = c >> 4, q = c & 15;
            cp16(b3B + kr * (BU_STR_F * 4) + q * 16,
                 W3 + (size_t)(k0 + kr) * H_DIM + n0 + q * 4);
        }
    };

    load_tile(0, 0);       CP_COMMIT();
    load_tile(1, BKT);     CP_COMMIT();

    float acc1[2][4][4] = {};
    float acc3[2][4][4] = {};

    const int lrow = lane >> 2;      // 0..7
    const int lcol = lane & 3;       // 0..3
    const int NT = D_DIM / BKT;      // 32

    for (int kt = 0; kt < NT; kt++) {
        const int cur = kt % 3;
        CP_WAIT1();
        __syncthreads();
        if (kt + 2 < NT) load_tile((kt + 2) % 3, (kt + 2) * BKT);
        CP_COMMIT();

        const char* aP  = (const char*)smem + (size_t)cur * STAGE_U;
        const char* b1P = aP + A_TILE_B;
        const char* b3P = b1P + BU_TILE_B;

#pragma unroll
        for (int ks = 0; ks < BKT / 8; ks++) {
            uint32_t a[2][4], b1[4][2], b3[4][2];
#pragma unroll
            for (int mt = 0; mt < 2; mt++) {
                int m = warp_m * 32 + mt * 16 + lrow;
                int k = ks * 8 + lcol;
                const uint32_t* r0 = (const uint32_t*)(aP + (size_t)m * (A_STR_F * 4));
                const uint32_t* r1 = (const uint32_t*)(aP + (size_t)(m + 8) * (A_STR_F * 4));
                a[mt][0] = r0[k];     a[mt][1] = r1[k];
                a[mt][2] = r0[k + 4]; a[mt][3] = r1[k + 4];
            }
#pragma unroll
            for (int nt = 0; nt < 4; nt++) {
                int n = warp_n * 32 + nt * 8 + lrow;
                int k = ks * 8 + lcol;
                b1[nt][0] = tf32u(((const uint32_t*)(b1P + (size_t)k * (BU_STR_F * 4)))[n]);
                b1[nt][1] = tf32u(((const uint32_t*)(b1P + (size_t)(k + 4) * (BU_STR_F * 4)))[n]);
                b3[nt][0] = tf32u(((const uint32_t*)(b3P + (size_t)k * (BU_STR_F * 4)))[n]);
                b3[nt][1] = tf32u(((const uint32_t*)(b3P + (size_t)(k + 4) * (BU_STR_F * 4)))[n]);
            }
#pragma unroll
            for (int mt = 0; mt < 2; mt++)
#pragma unroll
                for (int nt = 0; nt < 4; nt++) {
                    mma8(acc1[mt][nt], a[mt], b1[nt]);
                    mma8(acc3[mt][nt], a[mt], b3[nt]);
                }
        }
    }

    // epilogue: silu(u1)*u3 -> g_U (tf32-rounded for the down GEMM)
#pragma unroll
    for (int mt = 0; mt < 2; mt++) {
#pragma unroll
        for (int half = 0; half < 2; half++) {
            int r = warp_m * 32 + mt * 16 + lrow + half * 8;
            if (m0 + r < count) {
                float* urow = g_U + (size_t)sEnt[r] * H_DIM;
#pragma unroll
                for (int nt = 0; nt < 4; nt++) {
                    int cbase = n0 + warp_n * 32 + nt * 8 + 2 * lcol;
                    float z0 = acc1[mt][nt][half * 2 + 0];
                    float z1 = acc1[mt][nt][half * 2 + 1];
                    float2 o;
                    o.x = tf32r(z0 / (1.f + expf(-z0)) * acc3[mt][nt][half * 2 + 0]);
                    o.y = tf32r(z1 / (1.f + expf(-z1)) * acc3[mt][nt][half * 2 + 1]);
                    *(float2*)(urow + cbase) = o;
                }
            }
        }
    }
}

// ============================================================
// DOWN: per expert, Y = gate * (U@W2). CTA: M=128, N=128, K=512.
// 8 warps in 4(m)x2(n): warp tile 32m x 64n. 3-stage ring.
// ============================================================
__global__ __launch_bounds__(256, 1) void down_gemm_kernel(const float* __restrict__ w2) {
    const int e = blockIdx.z;
    const int count = g_count[e];
    const int m0 = blockIdx.x * 128;
    if (m0 >= count) return;
    const int n0 = blockIdx.y * 128;

    extern __shared__ __align__(128) char smem[];
    __shared__ int   sEnt[128];
    __shared__ float sGate[128];

    const int tid = threadIdx.x;
    const int wid = tid >> 5, lane = tid & 31;
    const int warp_m = wid >> 1, warp_n = wid & 1;

    uint32_t base = smem_u32(smem);

    if (tid < 128) {
        int p = m0 + tid;
        sEnt[tid]  = (p < count) ? g_entry[e][p] : g_entry[e][0];
        sGate[tid] = (p < count) ? g_gateW[e][p] : 0.f;
    }
    __syncthreads();

    const float* W2 = w2 + (size_t)e * H_DIM * D_DIM;

    auto load_tile = [&](int buf, int k0) {
        uint32_t aB = base + buf * STAGE_D;
        uint32_t bB = aB + A_TILE_B;
#pragma unroll
        for (int i = 0; i < 4; i++) {            // A: 128 rows x 8 chunks
            int c = tid + i * 256, row = c >> 3, q = c & 7;
            cp16(aB + row * (A_STR_F * 4) + q * 16,
                 g_U + (size_t)sEnt[row] * H_DIM + k0 + q * 4);
        }
#pragma unroll
        for (int i = 0; i < 4; i++) {            // B: 32 k-rows x 32 chunks
            int c = tid + i * 256, kr = c >> 5, q = c & 31;
            cp16(bB + kr * (BD_STR_F * 4) + q * 16,
                 W2 + (size_t)(k0 + kr) * D_DIM + n0 + q * 4);
        }
    };

    load_tile(0, 0);       CP_COMMIT();
    load_tile(1, BKT);     CP_COMMIT();

    float acc[2][8][4] = {};

    const int lrow = lane >> 2;
    const int lcol = lane & 3;
    const int NT = H_DIM / BKT;   // 16

    for (int kt = 0; kt < NT; kt++) {
        const int cur = kt % 3;
        CP_WAIT1();
        __syncthreads();
        if (kt + 2 < NT) load_tile((kt + 2) % 3, (kt + 2) * BKT);
        CP_COMMIT();

        const char* aP = (const char*)smem + (size_t)cur * STAGE_D;
        const char* bP = aP + A_TILE_B;

#pragma unroll
        for (int ks = 0; ks < BKT / 8; ks++) {
            uint32_t a[2][4], b[8][2];
#pragma unroll
            for (int mt = 0; mt < 2; mt++) {
                int m = warp_m * 32 + mt * 16 + lrow;
                int k = ks * 8 + lcol;
                const uint32_t* r0 = (const uint32_t*)(aP + (size_t)m * (A_STR_F * 4));
                const uint32_t* r1 = (const uint32_t*)(aP + (size_t)(m + 8) * (A_STR_F * 4));
                a[mt][0] = r0[k];     a[mt][1] = r1[k];
                a[mt][2] = r0[k + 4]; a[mt][3] = r1[k + 4];
            }
#pragma unroll
            for (int nt = 0; nt < 8; nt++) {
                int n = warp_n * 64 + nt * 8 + lrow;
                int k = ks * 8 + lcol;
                b[nt][0] = tf32u(((const uint32_t*)(bP + (size_t)k * (BD_STR_F * 4)))[n]);
                b[nt][1] = tf32u(((const uint32_t*)(bP + (size_t)(k + 4) * (BD_STR_F * 4)))[n]);
            }
#pragma unroll
            for (int mt = 0; mt < 2; mt++)
#pragma unroll
                for (int nt = 0; nt < 8; nt++)
                    mma8(acc[mt][nt], a[mt], b[nt]);
        }
    }

#pragma unroll
    for (int mt = 0; mt < 2; mt++) {
#pragma unroll
        for (int half = 0; half < 2; half++) {
            int r = warp_m * 32 + mt * 16 + lrow + half * 8;
            if (m0 + r < count) {
                float g = sGate[r];
                float* yrow = g_Y + (size_t)sEnt[r] * D_DIM;
#pragma unroll
                for (int nt = 0; nt < 8; nt++) {
                    int cbase = n0 + warp_n * 64 + nt * 8 + 2 * lcol;
                    float2 o;
                    o.x = g * acc[mt][nt][half * 2 + 0];
                    o.y = g * acc[mt][nt][half * 2 + 1];
                    *(float2*)(yrow + cbase) = o;
                }
            }
        }
    }
}

// ---------------- kernel: combine two slots per token ----------------
__global__ void combine_kernel(float* __restrict__ out) {
    size_t idx4 = (size_t)blockIdx.x * blockDim.x + threadIdx.x;
    size_t total4 = (size_t)T_TOK * D_DIM / 4;
    if (idx4 >= total4) return;
    size_t bofs = idx4 * 4;
    size_t t = bofs >> 10;
    size_t d = bofs & (D_DIM - 1);
    float4 a = *(const float4*)(g_Y + ((size_t)(2 * t) * D_DIM + d));
    float4 b = *(const float4*)(g_Y + ((size_t)(2 * t + 1) * D_DIM + d));
    float4 r;
    r.x = a.x + b.x; r.y = a.y + b.y; r.z = a.z + b.z; r.w = a.w + b.w;
    *(float4*)(out + bofs) = r;
}

// ---------------- launch ----------------
extern "C" void kernel_launch(void* const* d_in, const int* in_sizes, int n_in,
                              void* d_out, int out_size) {
    const float* x  = (const float*)d_in[0];
    const float* wr = (const float*)d_in[1];
    const float* w1 = (const float*)d_in[2];
    const float* w2 = (const float*)d_in[3];
    const float* w3 = (const float*)d_in[4];
    float* out = (float*)d_out;

    cudaFuncSetAttribute(up_gemm_kernel,   cudaFuncAttributeMaxDynamicSharedMemorySize, UP_SMEM);
    cudaFuncSetAttribute(down_gemm_kernel, cudaFuncAttributeMaxDynamicSharedMemorySize, DOWN_SMEM);

    zero_counts_kernel<<<1, 32>>>();
    router_kernel<<<T_TOK / 8, 256>>>(x, wr);

    {
        dim3 g(T_TOK / 128, H_DIM / 64, E_NUM);   // (64, 8, 8)
        up_gemm_kernel<<<g, 256, UP_SMEM>>>(w1, w3);
    }
    {
        dim3 g(T_TOK / 128, D_DIM / 128, E_NUM);  // (64, 8, 8)
        down_gemm_kernel<<<g, 256, DOWN_SMEM>>>(w2);
    }

    size_t total4 = (size_t)T_TOK * D_DIM / 4;
    combine_kernel<<<(unsigned)((total4 + 255) / 256), 256>>>(out);
}

// round 6
// speedup vs baseline: 3.4785x; 1.1532x over previous
#include <cuda_runtime.h>
#include <cstdint>
#include <math.h>

// ---------------- problem constants ----------------
#define T_TOK 8192
#define D_DIM 1024
#define E_NUM 8
#define H_DIM 512
#define NSLOT (2 * T_TOK)

// ---------------- device scratch (referenced ONLY from device code) ------
__device__ int   g_count[E_NUM];
__device__ int   g_entry[E_NUM][T_TOK];
__device__ float g_gateW[E_NUM][T_TOK];
__device__ __align__(16) float g_Xr[(size_t)T_TOK * D_DIM];           // tf32-rounded x
__device__ __align__(16) float g_w1r[(size_t)E_NUM * D_DIM * H_DIM];  // rounded weights
__device__ __align__(16) float g_w3r[(size_t)E_NUM * D_DIM * H_DIM];
__device__ __align__(16) float g_w2r[(size_t)E_NUM * H_DIM * D_DIM];
__device__ __align__(16) float g_U[(size_t)NSLOT * H_DIM];            // SwiGLU hidden (rounded)
__device__ __align__(16) float g_Y[(size_t)NSLOT * D_DIM];            // gated down-proj

// ---------------- helpers (sm_80-level PTX only) ----
__device__ __forceinline__ uint32_t smem_u32(const void* p) {
    uint32_t a;
    asm("{ .reg .u64 t; cvta.to.shared.u64 t, %1; cvt.u32.u64 %0, t; }" : "=r"(a) : "l"(p));
    return a;
}
__device__ __forceinline__ float tf32r(float v) {
    uint32_t u;
    asm("cvt.rna.tf32.f32 %0, %1;" : "=r"(u) : "f"(v));
    return __uint_as_float(u);
}
__device__ __forceinline__ void cp16(uint32_t dst, const void* src) {
    asm volatile("cp.async.cg.shared.global [%0], [%1], 16;" :: "r"(dst), "l"(src));
}
#define CP_COMMIT() asm volatile("cp.async.commit_group;" ::: "memory")
#define CP_WAIT1()  asm volatile("cp.async.wait_group 1;" ::: "memory")

// mma.sync m16n8k8 tf32: D = A*B + D
__device__ __forceinline__ void mma8(float* c, const uint32_t* a, const uint32_t* b) {
    asm volatile(
        "mma.sync.aligned.m16n8k8.row.col.f32.tf32.tf32.f32 "
        "{%0,%1,%2,%3}, {%4,%5,%6,%7}, {%8,%9}, {%0,%1,%2,%3};"
        : "+f"(c[0]), "+f"(c[1]), "+f"(c[2]), "+f"(c[3])
        : "r"(a[0]), "r"(a[1]), "r"(a[2]), "r"(a[3]), "r"(b[0]), "r"(b[1]));
}

// ---------------- kernel: zero counters ----------------
__global__ void zero_counts_kernel() {
    if (threadIdx.x < E_NUM) g_count[threadIdx.x] = 0;
}

// ---------------- kernel: router + fused tf32 round of x ----------------
__global__ void router_kernel(const float* __restrict__ x, const float* __restrict__ wr) {
    __shared__ float sWr[D_DIM * E_NUM];
    for (int i = threadIdx.x; i < D_DIM * E_NUM; i += blockDim.x) sWr[i] = wr[i];
    __syncthreads();

    int warp = threadIdx.x >> 5, lane = threadIdx.x & 31;
    int t = blockIdx.x * 8 + warp;
    if (t >= T_TOK) return;

    float acc[E_NUM];
#pragma unroll
    for (int e = 0; e < E_NUM; e++) acc[e] = 0.f;
    const float* xr = x + (size_t)t * D_DIM;
    float* xo = g_Xr + (size_t)t * D_DIM;
    for (int d = lane; d < D_DIM; d += 32) {
        float xv = xr[d];
        xo[d] = tf32r(xv);
#pragma unroll
        for (int e = 0; e < E_NUM; e++) acc[e] = fmaf(xv, sWr[d * E_NUM + e], acc[e]);
    }
#pragma unroll
    for (int off = 16; off > 0; off >>= 1)
#pragma unroll
        for (int e = 0; e < E_NUM; e++) acc[e] += __shfl_down_sync(0xffffffffu, acc[e], off);

    if (lane == 0) {
        float m = acc[0];
#pragma unroll
        for (int e = 1; e < E_NUM; e++) m = fmaxf(m, acc[e]);
        float p[E_NUM], s = 0.f;
#pragma unroll
        for (int e = 0; e < E_NUM; e++) { p[e] = expf(acc[e] - m); s += p[e]; }
        float inv = 1.f / s;
#pragma unroll
        for (int e = 0; e < E_NUM; e++) p[e] *= inv;

        int e0 = 0;
#pragma unroll
        for (int e = 1; e < E_NUM; e++) if (p[e] > p[e0]) e0 = e;
        int e1 = (e0 == 0) ? 1 : 0;
#pragma unroll
        for (int e = 0; e < E_NUM; e++) {
            if (e == e0) continue;
            if (p[e] > p[e1]) e1 = e;
        }
        int pos0 = atomicAdd(&g_count[e0], 1);
        g_entry[e0][pos0] = t * 2 + 0;
        g_gateW[e0][pos0] = p[e0];
        int pos1 = atomicAdd(&g_count[e1], 1);
        g_entry[e1][pos1] = t * 2 + 1;
        g_gateW[e1][pos1] = p[e1];
    }
}

// ---------------- kernel: round weights -> device globals ---------------
__global__ void round_w_kernel(const float* __restrict__ w1,
                               const float* __restrict__ w2,
                               const float* __restrict__ w3) {
    size_t i4 = (size_t)blockIdx.x * blockDim.x + threadIdx.x;
    size_t n4 = (size_t)E_NUM * D_DIM * H_DIM / 4;
    if (i4 >= n4) return;
    float4 a = *(const float4*)(w1 + i4 * 4);
    a.x = tf32r(a.x); a.y = tf32r(a.y); a.z = tf32r(a.z); a.w = tf32r(a.w);
    *(float4*)(g_w1r + i4 * 4) = a;
    float4 b = *(const float4*)(w3 + i4 * 4);
    b.x = tf32r(b.x); b.y = tf32r(b.y); b.z = tf32r(b.z); b.w = tf32r(b.w);
    *(float4*)(g_w3r + i4 * 4) = b;
    float4 c = *(const float4*)(w2 + i4 * 4);
    c.x = tf32r(c.x); c.y = tf32r(c.y); c.z = tf32r(c.z); c.w = tf32r(c.w);
    *(float4*)(g_w2r + i4 * 4) = c;
}

// ---------------- GEMM tiling constants ----------------
#define BKT 32                          // K per smem tile
#define A_STR_F 36                      // A smem row stride (floats)
#define A_TILE_B (128 * A_STR_F * 4)    // 18432 B
#define BU_STR_F 72                     // up B smem row stride (floats)
#define BU_TILE_B (BKT * BU_STR_F * 4)  // 9216 B
#define BD_STR_F 136                    // down B smem row stride (floats)
#define BD_TILE_B (BKT * BD_STR_F * 4)  // 17408 B
#define STAGE_U (A_TILE_B + 2 * BU_TILE_B)  // 36864
#define STAGE_D (A_TILE_B + BD_TILE_B)      // 35840
#define UP_SMEM   (2 * STAGE_U)             // 73728
#define DOWN_SMEM (2 * STAGE_D)             // 71680

// ============================================================
// UP: per expert, U = silu(Xg@W1)*(Xg@W3). CTA: M=128, N=64 (each), K=1024.
// 8 warps 4(m)x2(n), 2-stage ring, 2 CTAs/SM for latency hiding.
// ============================================================
__global__ __launch_bounds__(256, 2) void up_gemm_kernel() {
    const int e = blockIdx.z;
    const int count = g_count[e];
    const int m0 = blockIdx.x * 128;
    if (m0 >= count) return;
    const int n0 = blockIdx.y * 64;

    extern __shared__ __align__(128) char smem[];
    __shared__ int sTok[128];
    __shared__ int sEnt[128];

    const int tid = threadIdx.x;
    const int wid = tid >> 5, lane = tid & 31;
    const int warp_m = wid >> 1, warp_n = wid & 1;

    uint32_t base = smem_u32(smem);

    if (tid < 128) {
        int p = m0 + tid;
        int ent = (p < count) ? g_entry[e][p] : g_entry[e][0];
        sEnt[tid] = ent;
        sTok[tid] = ent >> 1;
    }
    __syncthreads();

    const float* W1 = g_w1r + (size_t)e * D_DIM * H_DIM;
    const float* W3 = g_w3r + (size_t)e * D_DIM * H_DIM;

    auto load_tile = [&](int buf, int k0) {
        uint32_t aB  = base + buf * STAGE_U;
        uint32_t b1B = aB + A_TILE_B;
        uint32_t b3B = b1B + BU_TILE_B;
#pragma unroll
        for (int i = 0; i < 4; i++) {            // A: 128 rows x 8 chunks
            int c = tid + i * 256, row = c >> 3, q = c & 7;
            cp16(aB + row * (A_STR_F * 4) + q * 16,
                 g_Xr + (size_t)sTok[row] * D_DIM + k0 + q * 4);
        }
#pragma unroll
        for (int i = 0; i < 2; i++) {            // B1: 32 k-rows x 16 chunks
            int c = tid + i * 256, kr = c >> 4, q = c & 15;
            cp16(b1B + kr * (BU_STR_F * 4) + q * 16,
                 W1 + (size_t)(k0 + kr) * H_DIM + n0 + q * 4);
        }
#pragma unroll
        for (int i = 0; i < 2; i++) {            // B3
            int c = tid + i * 256, kr = c >> 4, q = c & 15;
            cp16(b3B + kr * (BU_STR_F * 4) + q * 16,
                 W3 + (size_t)(k0 + kr) * H_DIM + n0 + q * 4);
        }
        CP_COMMIT();
    };

    load_tile(0, 0);
    load_tile(1, BKT);

    float acc1[2][4][4] = {};
    float acc3[2][4][4] = {};

    const int lrow = lane >> 2;      // 0..7
    const int lcol = lane & 3;       // 0..3
    const int NT = D_DIM / BKT;      // 32

    for (int kt = 0; kt < NT; kt++) {
        const int cur = kt & 1;
        CP_WAIT1();
        __syncthreads();

        const char* aP  = (const char*)smem + (size_t)cur * STAGE_U;
        const char* b1P = aP + A_TILE_B;
        const char* b3P = b1P + BU_TILE_B;

#pragma unroll
        for (int ks = 0; ks < BKT / 8; ks++) {
            uint32_t a[2][4], b1[4][2], b3[4][2];
#pragma unroll
            for (int mt = 0; mt < 2; mt++) {
                int m = warp_m * 32 + mt * 16 + lrow;
                int k = ks * 8 + lcol;
                const uint32_t* r0 = (const uint32_t*)(aP + (size_t)m * (A_STR_F * 4));
                const uint32_t* r1 = (const uint32_t*)(aP + (size_t)(m + 8) * (A_STR_F * 4));
                a[mt][0] = r0[k];     a[mt][1] = r1[k];
                a[mt][2] = r0[k + 4]; a[mt][3] = r1[k + 4];
            }
#pragma unroll
            for (int nt = 0; nt < 4; nt++) {
                int n = warp_n * 32 + nt * 8 + lrow;
                int k = ks * 8 + lcol;
                b1[nt][0] = ((const uint32_t*)(b1P + (size_t)k * (BU_STR_F * 4)))[n];
                b1[nt][1] = ((const uint32_t*)(b1P + (size_t)(k + 4) * (BU_STR_F * 4)))[n];
                b3[nt][0] = ((const uint32_t*)(b3P + (size_t)k * (BU_STR_F * 4)))[n];
                b3[nt][1] = ((const uint32_t*)(b3P + (size_t)(k + 4) * (BU_STR_F * 4)))[n];
            }
#pragma unroll
            for (int mt = 0; mt < 2; mt++)
#pragma unroll
                for (int nt = 0; nt < 4; nt++) {
                    mma8(acc1[mt][nt], a[mt], b1[nt]);
                    mma8(acc3[mt][nt], a[mt], b3[nt]);
                }
        }
        __syncthreads();
        if (kt + 2 < NT) load_tile(cur, (kt + 2) * BKT);
        else CP_COMMIT();
    }

    // epilogue: silu(u1)*u3 -> g_U (tf32-rounded for the down GEMM)
#pragma unroll
    for (int mt = 0; mt < 2; mt++) {
#pragma unroll
        for (int half = 0; half < 2; half++) {
            int r = warp_m * 32 + mt * 16 + lrow + half * 8;
            if (m0 + r < count) {
                float* urow = g_U + (size_t)sEnt[r] * H_DIM;
#pragma unroll
                for (int nt = 0; nt < 4; nt++) {
                    int cbase = n0 + warp_n * 32 + nt * 8 + 2 * lcol;
                    float z0 = acc1[mt][nt][half * 2 + 0];
                    float z1 = acc1[mt][nt][half * 2 + 1];
                    float2 o;
                    o.x = tf32r(z0 / (1.f + expf(-z0)) * acc3[mt][nt][half * 2 + 0]);
                    o.y = tf32r(z1 / (1.f + expf(-z1)) * acc3[mt][nt][half * 2 + 1]);
                    *(float2*)(urow + cbase) = o;
                }
            }
        }
    }
}

// ============================================================
// DOWN: per expert, Y = gate * (U@W2). CTA: M=128, N=128, K=512.
// 8 warps 4(m)x2(n): warp tile 32m x 64n. 2-stage ring, 2 CTAs/SM.
// ============================================================
__global__ __launch_bounds__(256, 2) void down_gemm_kernel() {
    const int e = blockIdx.z;
    const int count = g_count[e];
    const int m0 = blockIdx.x * 128;
    if (m0 >= count) return;
    const int n0 = blockIdx.y * 128;

    extern __shared__ __align__(128) char smem[];
    __shared__ int   sEnt[128];
    __shared__ float sGate[128];

    const int tid = threadIdx.x;
    const int wid = tid >> 5, lane = tid & 31;
    const int warp_m = wid >> 1, warp_n = wid & 1;

    uint32_t base = smem_u32(smem);

    if (tid < 128) {
        int p = m0 + tid;
        sEnt[tid]  = (p < count) ? g_entry[e][p] : g_entry[e][0];
        sGate[tid] = (p < count) ? g_gateW[e][p] : 0.f;
    }
    __syncthreads();

    const float* W2 = g_w2r + (size_t)e * H_DIM * D_DIM;

    auto load_tile = [&](int buf, int k0) {
        uint32_t aB = base + buf * STAGE_D;
        uint32_t bB = aB + A_TILE_B;
#pragma unroll
        for (int i = 0; i < 4; i++) {            // A: 128 rows x 8 chunks
            int c = tid + i * 256, row = c >> 3, q = c & 7;
            cp16(aB + row * (A_STR_F * 4) + q * 16,
                 g_U + (size_t)sEnt[row] * H_DIM + k0 + q * 4);
        }
#pragma unroll
        for (int i = 0; i < 4; i++) {            // B: 32 k-rows x 32 chunks
            int c = tid + i * 256, kr = c >> 5, q = c & 31;
            cp16(bB + kr * (BD_STR_F * 4) + q * 16,
                 W2 + (size_t)(k0 + kr) * D_DIM + n0 + q * 4);
        }
        CP_COMMIT();
    };

    load_tile(0, 0);
    load_tile(1, BKT);

    float acc[2][8][4] = {};

    const int lrow = lane >> 2;
    const int lcol = lane & 3;
    const int NT = H_DIM / BKT;   // 16

    for (int kt = 0; kt < NT; kt++) {
        const int cur = kt & 1;
        CP_WAIT1();
        __syncthreads();

        const char* aP = (const char*)smem + (size_t)cur * STAGE_D;
        const char* bP = aP + A_TILE_B;

#pragma unroll
        for (int ks = 0; ks < BKT / 8; ks++) {
            uint32_t a[2][4], b[8][2];
#pragma unroll
            for (int mt = 0; mt < 2; mt++) {
                int m = warp_m * 32 + mt * 16 + lrow;
                int k = ks * 8 + lcol;
                const uint32_t* r0 = (const uint32_t*)(aP + (size_t)m * (A_STR_F * 4));
                const uint32_t* r1 = (const uint32_t*)(aP + (size_t)(m + 8) * (A_STR_F * 4));
                a[mt][0] = r0[k];     a[mt][1] = r1[k];
                a[mt][2] = r0[k + 4]; a[mt][3] = r1[k + 4];
            }
#pragma unroll
            for (int nt = 0; nt < 8; nt++) {
                int n = warp_n * 64 + nt * 8 + lrow;
                int k = ks * 8 + lcol;
                b[nt][0] = ((const uint32_t*)(bP + (size_t)k * (BD_STR_F * 4)))[n];
                b[nt][1] = ((const uint32_t*)(bP + (size_t)(k + 4) * (BD_STR_F * 4)))[n];
            }
#pragma unroll
            for (int mt = 0; mt < 2; mt++)
#pragma unroll
                for (int nt = 0; nt < 8; nt++)
                    mma8(acc[mt][nt], a[mt], b[nt]);
        }
        __syncthreads();
        if (kt + 2 < NT) load_tile(cur, (kt + 2) * BKT);
        else CP_COMMIT();
    }

#pragma unroll
    for (int mt = 0; mt < 2; mt++) {
#pragma unroll
        for (int half = 0; half < 2; half++) {
            int r = warp_m * 32 + mt * 16 + lrow + half * 8;
            if (m0 + r < count) {
                float g = sGate[r];
                float* yrow = g_Y + (size_t)sEnt[r] * D_DIM;
#pragma unroll
                for (int nt = 0; nt < 8; nt++) {
                    int cbase = n0 + warp_n * 64 + nt * 8 + 2 * lcol;
                    float2 o;
                    o.x = g * acc[mt][nt][half * 2 + 0];
                    o.y = g * acc[mt][nt][half * 2 + 1];
                    *(float2*)(yrow + cbase) = o;
                }
            }
        }
    }
}

// ---------------- kernel: combine two slots per token ----------------
__global__ void combine_kernel(float* __restrict__ out) {
    size_t idx4 = (size_t)blockIdx.x * blockDim.x + threadIdx.x;
    size_t total4 = (size_t)T_TOK * D_DIM / 4;
    if (idx4 >= total4) return;
    size_t bofs = idx4 * 4;
    size_t t = bofs >> 10;
    size_t d = bofs & (D_DIM - 1);
    float4 a = *(const float4*)(g_Y + ((size_t)(2 * t) * D_DIM + d));
    float4 b = *(const float4*)(g_Y + ((size_t)(2 * t + 1) * D_DIM + d));
    float4 r;
    r.x = a.x + b.x; r.y = a.y + b.y; r.z = a.z + b.z; r.w = a.w + b.w;
    *(float4*)(out + bofs) = r;
}

// ---------------- launch ----------------
extern "C" void kernel_launch(void* const* d_in, const int* in_sizes, int n_in,
                              void* d_out, int out_size) {
    const float* x  = (const float*)d_in[0];
    const float* wr = (const float*)d_in[1];
    const float* w1 = (const float*)d_in[2];
    const float* w2 = (const float*)d_in[3];
    const float* w3 = (const float*)d_in[4];
    float* out = (float*)d_out;

    cudaFuncSetAttribute(up_gemm_kernel,   cudaFuncAttributeMaxDynamicSharedMemorySize, UP_SMEM);
    cudaFuncSetAttribute(down_gemm_kernel, cudaFuncAttributeMaxDynamicSharedMemorySize, DOWN_SMEM);

    zero_counts_kernel<<<1, 32>>>();
    router_kernel<<<T_TOK / 8, 256>>>(x, wr);

    {
        int n4 = E_NUM * D_DIM * H_DIM / 4;   // 1M float4 per weight tensor
        round_w_kernel<<<(n4 + 255) / 256, 256>>>(w1, w2, w3);
    }

    {
        dim3 g(T_TOK / 128, H_DIM / 64, E_NUM);   // (64, 8, 8)
        up_gemm_kernel<<<g, 256, UP_SMEM>>>();
    }
    {
        dim3 g(T_TOK / 128, D_DIM / 128, E_NUM);  // (64, 8, 8)
        down_gemm_kernel<<<g, 256, DOWN_SMEM>>>();
    }

    size_t total4 = (size_t)T_TOK * D_DIM / 4;
    combine_kernel<<<(unsigned)((total4 + 255) / 256), 256>>>(out);
}

// round 7
// speedup vs baseline: 3.5346x; 1.0161x over previous
#include <cuda_runtime.h>
#include <cstdint>
#include <math.h>

// ---------------- problem constants ----------------
#define T_TOK 8192
#define D_DIM 1024
#define E_NUM 8
#define H_DIM 512
#define NSLOT (2 * T_TOK)

// ---------------- device scratch (referenced ONLY from device code) ------
__device__ int   g_count[E_NUM];
__device__ int   g_entry[E_NUM][T_TOK];
__device__ float g_gateW[E_NUM][T_TOK];
__device__ __align__(16) float g_Xr[(size_t)T_TOK * D_DIM];           // tf32-rounded x
__device__ __align__(16) float g_w1t[(size_t)E_NUM * H_DIM * D_DIM];  // [e][h][d] rounded+T
__device__ __align__(16) float g_w3t[(size_t)E_NUM * H_DIM * D_DIM];  // [e][h][d]
__device__ __align__(16) float g_w2t[(size_t)E_NUM * D_DIM * H_DIM];  // [e][d][h]
__device__ __align__(16) float g_U[(size_t)NSLOT * H_DIM];            // SwiGLU hidden (rounded)
__device__ __align__(16) float g_Y[(size_t)NSLOT * D_DIM];            // gated down-proj

// ---------------- helpers (sm_80-level PTX only) ----
__device__ __forceinline__ uint32_t smem_u32(const void* p) {
    uint32_t a;
    asm("{ .reg .u64 t; cvta.to.shared.u64 t, %1; cvt.u32.u64 %0, t; }" : "=r"(a) : "l"(p));
    return a;
}
__device__ __forceinline__ float tf32r(float v) {
    uint32_t u;
    asm("cvt.rna.tf32.f32 %0, %1;" : "=r"(u) : "f"(v));
    return __uint_as_float(u);
}
__device__ __forceinline__ void cp16(uint32_t dst, const void* src) {
    asm volatile("cp.async.cg.shared.global [%0], [%1], 16;" :: "r"(dst), "l"(src));
}
#define CP_COMMIT() asm volatile("cp.async.commit_group;" ::: "memory")
#define CP_WAIT1()  asm volatile("cp.async.wait_group 1;" ::: "memory")

// ldmatrix x4: four 8x4-of-b32 matrices (as 8x8 b16), one per output reg
__device__ __forceinline__ void ldsm4(uint32_t* r, uint32_t addr) {
    asm volatile("ldmatrix.sync.aligned.m8n8.x4.shared.b16 {%0,%1,%2,%3}, [%4];"
        : "=r"(r[0]), "=r"(r[1]), "=r"(r[2]), "=r"(r[3]) : "r"(addr));
}

// mma.sync m16n8k8 tf32: D = A*B + D
__device__ __forceinline__ void mma8(float* c, const uint32_t* a, const uint32_t* b) {
    asm volatile(
        "mma.sync.aligned.m16n8k8.row.col.f32.tf32.tf32.f32 "
        "{%0,%1,%2,%3}, {%4,%5,%6,%7}, {%8,%9}, {%0,%1,%2,%3};"
        : "+f"(c[0]), "+f"(c[1]), "+f"(c[2]), "+f"(c[3])
        : "r"(a[0]), "r"(a[1]), "r"(a[2]), "r"(a[3]), "r"(b[0]), "r"(b[1]));
}

// ---------------- kernel: zero counters ----------------
__global__ void zero_counts_kernel() {
    if (threadIdx.x < E_NUM) g_count[threadIdx.x] = 0;
}

// ---------------- kernel: router + fused tf32 round of x ----------------
__global__ void router_kernel(const float* __restrict__ x, const float* __restrict__ wr) {
    __shared__ float sWr[D_DIM * E_NUM];
    for (int i = threadIdx.x; i < D_DIM * E_NUM; i += blockDim.x) sWr[i] = wr[i];
    __syncthreads();

    int warp = threadIdx.x >> 5, lane = threadIdx.x & 31;
    int t = blockIdx.x * 8 + warp;
    if (t >= T_TOK) return;

    float acc[E_NUM];
#pragma unroll
    for (int e = 0; e < E_NUM; e++) acc[e] = 0.f;
    const float* xr = x + (size_t)t * D_DIM;
    float* xo = g_Xr + (size_t)t * D_DIM;
    for (int d = lane; d < D_DIM; d += 32) {
        float xv = xr[d];
        xo[d] = tf32r(xv);
#pragma unroll
        for (int e = 0; e < E_NUM; e++) acc[e] = fmaf(xv, sWr[d * E_NUM + e], acc[e]);
    }
#pragma unroll
    for (int off = 16; off > 0; off >>= 1)
#pragma unroll
        for (int e = 0; e < E_NUM; e++) acc[e] += __shfl_down_sync(0xffffffffu, acc[e], off);

    if (lane == 0) {
        float m = acc[0];
#pragma unroll
        for (int e = 1; e < E_NUM; e++) m = fmaxf(m, acc[e]);
        float p[E_NUM], s = 0.f;
#pragma unroll
        for (int e = 0; e < E_NUM; e++) { p[e] = expf(acc[e] - m); s += p[e]; }
        float inv = 1.f / s;
#pragma unroll
        for (int e = 0; e < E_NUM; e++) p[e] *= inv;

        int e0 = 0;
#pragma unroll
        for (int e = 1; e < E_NUM; e++) if (p[e] > p[e0]) e0 = e;
        int e1 = (e0 == 0) ? 1 : 0;
#pragma unroll
        for (int e = 0; e < E_NUM; e++) {
            if (e == e0) continue;
            if (p[e] > p[e1]) e1 = e;
        }
        int pos0 = atomicAdd(&g_count[e0], 1);
        g_entry[e0][pos0] = t * 2 + 0;
        g_gateW[e0][pos0] = p[e0];
        int pos1 = atomicAdd(&g_count[e1], 1);
        g_entry[e1][pos1] = t * 2 + 1;
        g_gateW[e1][pos1] = p[e1];
    }
}

// ---------------- kernel: transpose + tf32 round weights ----------------
// in[z][R][C] -> out[z][C][R]; which selects destination global.
__global__ void transpose_w_kernel(const float* __restrict__ in, int which, int R, int C) {
    __shared__ float tile[32][33];
    int r0 = blockIdx.y * 32, c0 = blockIdx.x * 32;
    const float* ip = in + (size_t)blockIdx.z * R * C;
    float* out = (which == 0) ? g_w1t : (which == 1) ? g_w3t : g_w2t;
    float* op = out + (size_t)blockIdx.z * R * C;
    int tx = threadIdx.x, ty = threadIdx.y;
#pragma unroll
    for (int i = 0; i < 32; i += 8)
        tile[ty + i][tx] = tf32r(ip[(size_t)(r0 + ty + i) * C + (c0 + tx)]);
    __syncthreads();
#pragma unroll
    for (int i = 0; i < 32; i += 8)
        op[(size_t)(c0 + ty + i) * R + (r0 + tx)] = tile[tx][ty + i];
}

// ---------------- GEMM tiling constants ----------------
#define BKT 32                          // K per smem tile
#define STR_F 36                        // smem row stride (floats) -> 144B
#define STR_B (STR_F * 4)
#define A_TILE_B (128 * STR_B)          // 18432 B
#define BU_TILE_B (64 * STR_B)          // 9216 B  (64 n-rows)
#define BD_TILE_B (128 * STR_B)         // 18432 B (128 n-rows)
#define STAGE_U (A_TILE_B + 2 * BU_TILE_B)  // 36864
#define STAGE_D (A_TILE_B + BD_TILE_B)      // 36864
#define UP_SMEM   (2 * STAGE_U)             // 73728
#define DOWN_SMEM (2 * STAGE_D)             // 73728

// ============================================================
// UP: per expert, U = silu(Xg@W1)*(Xg@W3). CTA: M=128, N=64 (each), K=1024.
// 8 warps 4(m)x2(n). Fragments via ldmatrix.x4 (A [m][k], B [n][k], stride 144B).
// ============================================================
__global__ __launch_bounds__(256, 2) void up_gemm_kernel() {
    const int e = blockIdx.z;
    const int count = g_count[e];
    const int m0 = blockIdx.x * 128;
    if (m0 >= count) return;
    const int n0 = blockIdx.y * 64;

    extern __shared__ __align__(128) char smem[];
    __shared__ int sTok[128];
    __shared__ int sEnt[128];

    const int tid = threadIdx.x;
    const int wid = tid >> 5, lane = tid & 31;
    const int warp_m = wid >> 1, warp_n = wid & 1;

    uint32_t base = smem_u32(smem);

    if (tid < 128) {
        int p = m0 + tid;
        int ent = (p < count) ? g_entry[e][p] : g_entry[e][0];
        sEnt[tid] = ent;
        sTok[tid] = ent >> 1;
    }
    __syncthreads();

    const float* W1 = g_w1t + (size_t)e * H_DIM * D_DIM;   // [h][d]
    const float* W3 = g_w3t + (size_t)e * H_DIM * D_DIM;

    auto load_tile = [&](int buf, int k0) {
        uint32_t aB  = base + buf * STAGE_U;
        uint32_t b1B = aB + A_TILE_B;
        uint32_t b3B = b1B + BU_TILE_B;
#pragma unroll
        for (int i = 0; i < 4; i++) {            // A: 128 rows x 8 chunks
            int c = tid + i * 256, row = c >> 3, q = c & 7;
            cp16(aB + row * STR_B + q * 16,
                 g_Xr + (size_t)sTok[row] * D_DIM + k0 + q * 4);
        }
#pragma unroll
        for (int i = 0; i < 2; i++) {            // B1: 64 n-rows x 8 chunks
            int c = tid + i * 256, row = c >> 3, q = c & 7;
            cp16(b1B + row * STR_B + q * 16,
                 W1 + (size_t)(n0 + row) * D_DIM + k0 + q * 4);
        }
#pragma unroll
        for (int i = 0; i < 2; i++) {            // B3
            int c = tid + i * 256, row = c >> 3, q = c & 7;
            cp16(b3B + row * STR_B + q * 16,
                 W3 + (size_t)(n0 + row) * D_DIM + k0 + q * 4);
        }
        CP_COMMIT();
    };

    load_tile(0, 0);
    load_tile(1, BKT);

    float acc1[2][4][4] = {};
    float acc3[2][4][4] = {};

    // per-lane ldmatrix offsets (relative to tile starts), loop-invariant
    const int j = lane;
    // A mt: row = warp_m*32 + mt*16 + ((j>>3)&1)*8 + (j&7); kbyte = ((j>>4)&1)*16
    uint32_t aOff0 = (uint32_t)(warp_m * 32 +      ((j >> 3) & 1) * 8 + (j & 7)) * STR_B + ((j >> 4) & 1) * 16;
    uint32_t aOff1 = aOff0 + 16 * STR_B;
    // B pair p: n = warp_n*32 + p*16 + ((j>>4)&1)*8 + (j&7); kbyte = ((j>>3)&1)*16
    uint32_t bOff0 = (uint32_t)(warp_n * 32 +      ((j >> 4) & 1) * 8 + (j & 7)) * STR_B + ((j >> 3) & 1) * 16;
    uint32_t bOff1 = bOff0 + 16 * STR_B;

    const int lrow = lane >> 2;
    const int lcol = lane & 3;
    const int NT = D_DIM / BKT;      // 32

    for (int kt = 0; kt < NT; kt++) {
        const int cur = kt & 1;
        CP_WAIT1();
        __syncthreads();

        uint32_t aS  = base + cur * STAGE_U;
        uint32_t b1S = aS + A_TILE_B;
        uint32_t b3S = b1S + BU_TILE_B;

#pragma unroll
        for (int ks = 0; ks < BKT / 8; ks++) {
            uint32_t a[2][4], b1[2][4], b3[2][4];
            ldsm4(a[0],  aS  + aOff0 + ks * 32);
            ldsm4(a[1],  aS  + aOff1 + ks * 32);
            ldsm4(b1[0], b1S + bOff0 + ks * 32);
            ldsm4(b1[1], b1S + bOff1 + ks * 32);
            ldsm4(b3[0], b3S + bOff0 + ks * 32);
            ldsm4(b3[1], b3S + bOff1 + ks * 32);
#pragma unroll
            for (int mt = 0; mt < 2; mt++)
#pragma unroll
                for (int p = 0; p < 2; p++) {
                    mma8(acc1[mt][2 * p + 0], a[mt], &b1[p][0]);
                    mma8(acc1[mt][2 * p + 1], a[mt], &b1[p][2]);
                    mma8(acc3[mt][2 * p + 0], a[mt], &b3[p][0]);
                    mma8(acc3[mt][2 * p + 1], a[mt], &b3[p][2]);
                }
        }
        __syncthreads();
        if (kt + 2 < NT) load_tile(cur, (kt + 2) * BKT);
        else CP_COMMIT();
    }

    // epilogue: silu(u1)*u3 -> g_U (tf32-rounded for the down GEMM)
#pragma unroll
    for (int mt = 0; mt < 2; mt++) {
#pragma unroll
        for (int half = 0; half < 2; half++) {
            int r = warp_m * 32 + mt * 16 + lrow + half * 8;
            if (m0 + r < count) {
                float* urow = g_U + (size_t)sEnt[r] * H_DIM;
#pragma unroll
                for (int nt = 0; nt < 4; nt++) {
                    int cbase = n0 + warp_n * 32 + nt * 8 + 2 * lcol;
                    float z0 = acc1[mt][nt][half * 2 + 0];
                    float z1 = acc1[mt][nt][half * 2 + 1];
                    float2 o;
                    o.x = tf32r(z0 / (1.f + expf(-z0)) * acc3[mt][nt][half * 2 + 0]);
                    o.y = tf32r(z1 / (1.f + expf(-z1)) * acc3[mt][nt][half * 2 + 1]);
                    *(float2*)(urow + cbase) = o;
                }
            }
        }
    }
}

// ============================================================
// DOWN: per expert, Y = gate * (U@W2). CTA: M=128, N=128, K=512.
// 8 warps 4(m)x2(n): warp tile 32m x 64n. ldmatrix fragments.
// ============================================================
__global__ __launch_bounds__(256, 2) void down_gemm_kernel() {
    const int e = blockIdx.z;
    const int count = g_count[e];
    const int m0 = blockIdx.x * 128;
    if (m0 >= count) return;
    const int n0 = blockIdx.y * 128;

    extern __shared__ __align__(128) char smem[];
    __shared__ int   sEnt[128];
    __shared__ float sGate[128];

    const int tid = threadIdx.x;
    const int wid = tid >> 5, lane = tid & 31;
    const int warp_m = wid >> 1, warp_n = wid & 1;

    uint32_t base = smem_u32(smem);

    if (tid < 128) {
        int p = m0 + tid;
        sEnt[tid]  = (p < count) ? g_entry[e][p] : g_entry[e][0];
        sGate[tid] = (p < count) ? g_gateW[e][p] : 0.f;
    }
    __syncthreads();

    const float* W2 = g_w2t + (size_t)e * D_DIM * H_DIM;   // [d][h]

    auto load_tile = [&](int buf, int k0) {
        uint32_t aB = base + buf * STAGE_D;
        uint32_t bB = aB + A_TILE_B;
#pragma unroll
        for (int i = 0; i < 4; i++) {            // A: 128 rows x 8 chunks
            int c = tid + i * 256, row = c >> 3, q = c & 7;
            cp16(aB + row * STR_B + q * 16,
                 g_U + (size_t)sEnt[row] * H_DIM + k0 + q * 4);
        }
#pragma unroll
        for (int i = 0; i < 4; i++) {            // B: 128 n-rows x 8 chunks
            int c = tid + i * 256, row = c >> 3, q = c & 7;
            cp16(bB + row * STR_B + q * 16,
                 W2 + (size_t)(n0 + row) * H_DIM + k0 + q * 4);
        }
        CP_COMMIT();
    };

    load_tile(0, 0);
    load_tile(1, BKT);

    float acc[2][8][4] = {};

    const int j = lane;
    uint32_t aOff0 = (uint32_t)(warp_m * 32 + ((j >> 3) & 1) * 8 + (j & 7)) * STR_B + ((j >> 4) & 1) * 16;
    uint32_t aOff1 = aOff0 + 16 * STR_B;
    uint32_t bOffBase = (uint32_t)(warp_n * 64 + ((j >> 4) & 1) * 8 + (j & 7)) * STR_B + ((j >> 3) & 1) * 16;

    const int lrow = lane >> 2;
    const int lcol = lane & 3;
    const int NT = H_DIM / BKT;   // 16

    for (int kt = 0; kt < NT; kt++) {
        const int cur = kt & 1;
        CP_WAIT1();
        __syncthreads();

        uint32_t aS = base + cur * STAGE_D;
        uint32_t bS = aS + A_TILE_B;

#pragma unroll
        for (int ks = 0; ks < BKT / 8; ks++) {
            uint32_t a[2][4], b[4][4];
            ldsm4(a[0], aS + aOff0 + ks * 32);
            ldsm4(a[1], aS + aOff1 + ks * 32);
#pragma unroll
            for (int p = 0; p < 4; p++)
                ldsm4(b[p], bS + bOffBase + p * (16 * STR_B) + ks * 32);
#pragma unroll
            for (int mt = 0; mt < 2; mt++)
#pragma unroll
                for (int p = 0; p < 4; p++) {
                    mma8(acc[mt][2 * p + 0], a[mt], &b[p][0]);
                    mma8(acc[mt][2 * p + 1], a[mt], &b[p][2]);
                }
        }
        __syncthreads();
        if (kt + 2 < NT) load_tile(cur, (kt + 2) * BKT);
        else CP_COMMIT();
    }

#pragma unroll
    for (int mt = 0; mt < 2; mt++) {
#pragma unroll
        for (int half = 0; half < 2; half++) {
            int r = warp_m * 32 + mt * 16 + lrow + half * 8;
            if (m0 + r < count) {
                float g = sGate[r];
                float* yrow = g_Y + (size_t)sEnt[r] * D_DIM;
#pragma unroll
                for (int nt = 0; nt < 8; nt++) {
                    int cbase = n0 + warp_n * 64 + nt * 8 + 2 * lcol;
                    float2 o;
                    o.x = g * acc[mt][nt][half * 2 + 0];
                    o.y = g * acc[mt][nt][half * 2 + 1];
                    *(float2*)(yrow + cbase) = o;
                }
            }
        }
    }
}

// ---------------- kernel: combine two slots per token ----------------
__global__ void combine_kernel(float* __restrict__ out) {
    size_t idx4 = (size_t)blockIdx.x * blockDim.x + threadIdx.x;
    size_t total4 = (size_t)T_TOK * D_DIM / 4;
    if (idx4 >= total4) return;
    size_t bofs = idx4 * 4;
    size_t t = bofs >> 10;
    size_t d = bofs & (D_DIM - 1);
    float4 a = *(const float4*)(g_Y + ((size_t)(2 * t) * D_DIM + d));
    float4 b = *(const float4*)(g_Y + ((size_t)(2 * t + 1) * D_DIM + d));
    float4 r;
    r.x = a.x + b.x; r.y = a.y + b.y; r.z = a.z + b.z; r.w = a.w + b.w;
    *(float4*)(out + bofs) = r;
}

// ---------------- launch ----------------
extern "C" void kernel_launch(void* const* d_in, const int* in_sizes, int n_in,
                              void* d_out, int out_size) {
    const float* x  = (const float*)d_in[0];
    const float* wr = (const float*)d_in[1];
    const float* w1 = (const float*)d_in[2];
    const float* w2 = (const float*)d_in[3];
    const float* w3 = (const float*)d_in[4];
    float* out = (float*)d_out;

    cudaFuncSetAttribute(up_gemm_kernel,   cudaFuncAttributeMaxDynamicSharedMemorySize, UP_SMEM);
    cudaFuncSetAttribute(down_gemm_kernel, cudaFuncAttributeMaxDynamicSharedMemorySize, DOWN_SMEM);

    zero_counts_kernel<<<1, 32>>>();
    router_kernel<<<T_TOK / 8, 256>>>(x, wr);

    {   // w1 [e][1024][512] -> g_w1t [e][512][1024]; same for w3; w2 [e][512][1024] -> g_w2t [e][1024][512]
        dim3 b(32, 8);
        dim3 g13(512 / 32, 1024 / 32, E_NUM);
        transpose_w_kernel<<<g13, b>>>(w1, 0, 1024, 512);
        transpose_w_kernel<<<g13, b>>>(w3, 1, 1024, 512);
        dim3 g2(1024 / 32, 512 / 32, E_NUM);
        transpose_w_kernel<<<g2, b>>>(w2, 2, 512, 1024);
    }

    {
        dim3 g(T_TOK / 128, H_DIM / 64, E_NUM);   // (64, 8, 8)
        up_gemm_kernel<<<g, 256, UP_SMEM>>>();
    }
    {
        dim3 g(T_TOK / 128, D_DIM / 128, E_NUM);  // (64, 8, 8)
        down_gemm_kernel<<<g, 256, DOWN_SMEM>>>();
    }

    size_t total4 = (size_t)T_TOK * D_DIM / 4;
    combine_kernel<<<(unsigned)((total4 + 255) / 256), 256>>>(out);
}

// round 8
// speedup vs baseline: 5.5556x; 1.5718x over previous
#include <cuda_runtime.h>
#include <cuda_fp16.h>
#include <cstdint>
#include <math.h>

// ---------------- problem constants ----------------
#define T_TOK 8192
#define D_DIM 1024
#define E_NUM 8
#define H_DIM 512
#define NSLOT (2 * T_TOK)

// ---------------- device scratch (referenced ONLY from device code) ------
__device__ int   g_count[E_NUM];
__device__ int   g_entry[E_NUM][T_TOK];
__device__ float g_gateW[E_NUM][T_TOK];
__device__ __align__(16) __half g_Xh[(size_t)T_TOK * D_DIM];           // fp16 x
__device__ __align__(16) __half g_w1t[(size_t)E_NUM * H_DIM * D_DIM];  // [e][h][d] fp16 (k=d contiguous)
__device__ __align__(16) __half g_w3t[(size_t)E_NUM * H_DIM * D_DIM];  // [e][h][d]
__device__ __align__(16) __half g_w2t[(size_t)E_NUM * D_DIM * H_DIM];  // [e][d][h]
__device__ __align__(16) __half g_U[(size_t)NSLOT * H_DIM];            // SwiGLU hidden fp16
__device__ __align__(16) float  g_Y[(size_t)NSLOT * D_DIM];            // gated down-proj fp32

// ---------------- helpers (sm_80-level PTX only) ----
__device__ __forceinline__ uint32_t smem_u32(const void* p) {
    uint32_t a;
    asm("{ .reg .u64 t; cvta.to.shared.u64 t, %1; cvt.u32.u64 %0, t; }" : "=r"(a) : "l"(p));
    return a;
}
__device__ __forceinline__ void cp16(uint32_t dst, const void* src) {
    asm volatile("cp.async.cg.shared.global [%0], [%1], 16;" :: "r"(dst), "l"(src));
}
#define CP_COMMIT() asm volatile("cp.async.commit_group;" ::: "memory")
#define CP_WAIT1()  asm volatile("cp.async.wait_group 1;" ::: "memory")

// ldmatrix x4: four 8x8 b16 matrices
__device__ __forceinline__ void ldsm4(uint32_t* r, uint32_t addr) {
    asm volatile("ldmatrix.sync.aligned.m8n8.x4.shared.b16 {%0,%1,%2,%3}, [%4];"
        : "=r"(r[0]), "=r"(r[1]), "=r"(r[2]), "=r"(r[3]) : "r"(addr));
}

// mma.sync m16n8k16 fp16 -> fp32: D = A*B + D
__device__ __forceinline__ void mma16(float* c, const uint32_t* a, const uint32_t* b) {
    asm volatile(
        "mma.sync.aligned.m16n8k16.row.col.f32.f16.f16.f32 "
        "{%0,%1,%2,%3}, {%4,%5,%6,%7}, {%8,%9}, {%0,%1,%2,%3};"
        : "+f"(c[0]), "+f"(c[1]), "+f"(c[2]), "+f"(c[3])
        : "r"(a[0]), "r"(a[1]), "r"(a[2]), "r"(a[3]), "r"(b[0]), "r"(b[1]));
}

// ---------------- kernel: zero counters ----------------
__global__ void zero_counts_kernel() {
    if (threadIdx.x < E_NUM) g_count[threadIdx.x] = 0;
}

// ---------------- kernel: router + fused fp16 convert of x ----------------
__global__ void router_kernel(const float* __restrict__ x, const float* __restrict__ wr) {
    __shared__ float sWr[D_DIM * E_NUM];
    for (int i = threadIdx.x; i < D_DIM * E_NUM; i += blockDim.x) sWr[i] = wr[i];
    __syncthreads();

    int warp = threadIdx.x >> 5, lane = threadIdx.x & 31;
    int t = blockIdx.x * 8 + warp;
    if (t >= T_TOK) return;

    float acc[E_NUM];
#pragma unroll
    for (int e = 0; e < E_NUM; e++) acc[e] = 0.f;
    const float* xr = x + (size_t)t * D_DIM;
    __half* xo = g_Xh + (size_t)t * D_DIM;
    for (int d = lane; d < D_DIM; d += 32) {
        float xv = xr[d];
        xo[d] = __float2half_rn(xv);
#pragma unroll
        for (int e = 0; e < E_NUM; e++) acc[e] = fmaf(xv, sWr[d * E_NUM + e], acc[e]);
    }
#pragma unroll
    for (int off = 16; off > 0; off >>= 1)
#pragma unroll
        for (int e = 0; e < E_NUM; e++) acc[e] += __shfl_down_sync(0xffffffffu, acc[e], off);

    if (lane == 0) {
        float m = acc[0];
#pragma unroll
        for (int e = 1; e < E_NUM; e++) m = fmaxf(m, acc[e]);
        float p[E_NUM], s = 0.f;
#pragma unroll
        for (int e = 0; e < E_NUM; e++) { p[e] = expf(acc[e] - m); s += p[e]; }
        float inv = 1.f / s;
#pragma unroll
        for (int e = 0; e < E_NUM; e++) p[e] *= inv;

        int e0 = 0;
#pragma unroll
        for (int e = 1; e < E_NUM; e++) if (p[e] > p[e0]) e0 = e;
        int e1 = (e0 == 0) ? 1 : 0;
#pragma unroll
        for (int e = 0; e < E_NUM; e++) {
            if (e == e0) continue;
            if (p[e] > p[e1]) e1 = e;
        }
        int pos0 = atomicAdd(&g_count[e0], 1);
        g_entry[e0][pos0] = t * 2 + 0;
        g_gateW[e0][pos0] = p[e0];
        int pos1 = atomicAdd(&g_count[e1], 1);
        g_entry[e1][pos1] = t * 2 + 1;
        g_gateW[e1][pos1] = p[e1];
    }
}

// ---------------- kernel: transpose + fp16 convert weights ----------------
// in float [z][R][C] -> out half [z][C][R]; which selects destination.
__global__ void transpose_w_kernel(const float* __restrict__ in, int which, int R, int C) {
    __shared__ float tile[32][33];
    int r0 = blockIdx.y * 32, c0 = blockIdx.x * 32;
    const float* ip = in + (size_t)blockIdx.z * R * C;
    __half* out = (which == 0) ? g_w1t : (which == 1) ? g_w3t : g_w2t;
    __half* op = out + (size_t)blockIdx.z * R * C;
    int tx = threadIdx.x, ty = threadIdx.y;
#pragma unroll
    for (int i = 0; i < 32; i += 8)
        tile[ty + i][tx] = ip[(size_t)(r0 + ty + i) * C + (c0 + tx)];
    __syncthreads();
#pragma unroll
    for (int i = 0; i < 32; i += 8)
        op[(size_t)(c0 + ty + i) * R + (r0 + tx)] = __float2half_rn(tile[tx][ty + i]);
}

// ---------------- GEMM tiling constants ----------------
#define BKT 64                          // K per smem tile (halves) = 128B of data/row
#define STR_B 144                       // smem row stride bytes (128 data + 16 pad)
#define A_TILE_B (128 * STR_B)          // 18432 B
#define BU_TILE_B (64 * STR_B)          // 9216 B
#define BD_TILE_B (128 * STR_B)         // 18432 B
#define STAGE_U (A_TILE_B + 2 * BU_TILE_B)  // 36864
#define STAGE_D (A_TILE_B + BD_TILE_B)      // 36864
#define UP_SMEM   (2 * STAGE_U)             // 73728
#define DOWN_SMEM (2 * STAGE_D)             // 73728

// ============================================================
// UP: per expert, U = silu(Xg@W1)*(Xg@W3). CTA: M=128, N=64 (each), K=1024.
// 8 warps 4(m)x2(n); fp16 m16n8k16; ldmatrix fragments; 2-stage ring.
// ============================================================
__global__ __launch_bounds__(256, 2) void up_gemm_kernel() {
    const int e = blockIdx.z;
    const int count = g_count[e];
    const int m0 = blockIdx.x * 128;
    if (m0 >= count) return;
    const int n0 = blockIdx.y * 64;

    extern __shared__ __align__(128) char smem[];
    __shared__ int sTok[128];
    __shared__ int sEnt[128];

    const int tid = threadIdx.x;
    const int wid = tid >> 5, lane = tid & 31;
    const int warp_m = wid >> 1, warp_n = wid & 1;

    uint32_t base = smem_u32(smem);

    if (tid < 128) {
        int p = m0 + tid;
        int ent = (p < count) ? g_entry[e][p] : g_entry[e][0];
        sEnt[tid] = ent;
        sTok[tid] = ent >> 1;
    }
    __syncthreads();

    const __half* W1 = g_w1t + (size_t)e * H_DIM * D_DIM;   // [h][d]
    const __half* W3 = g_w3t + (size_t)e * H_DIM * D_DIM;

    auto load_tile = [&](int buf, int k0) {      // k0 in halves
        uint32_t aB  = base + buf * STAGE_U;
        uint32_t b1B = aB + A_TILE_B;
        uint32_t b3B = b1B + BU_TILE_B;
#pragma unroll
        for (int i = 0; i < 4; i++) {            // A: 128 rows x 8 chunks of 16B (8 halves)
            int c = tid + i * 256, row = c >> 3, q = c & 7;
            cp16(aB + row * STR_B + q * 16,
                 g_Xh + (size_t)sTok[row] * D_DIM + k0 + q * 8);
        }
#pragma unroll
        for (int i = 0; i < 2; i++) {            // B1: 64 n-rows x 8 chunks
            int c = tid + i * 256, row = c >> 3, q = c & 7;
            cp16(b1B + row * STR_B + q * 16,
                 W1 + (size_t)(n0 + row) * D_DIM + k0 + q * 8);
        }
#pragma unroll
        for (int i = 0; i < 2; i++) {            // B3
            int c = tid + i * 256, row = c >> 3, q = c & 7;
            cp16(b3B + row * STR_B + q * 16,
                 W3 + (size_t)(n0 + row) * D_DIM + k0 + q * 8);
        }
        CP_COMMIT();
    };

    load_tile(0, 0);
    load_tile(1, BKT);

    float acc1[2][4][4] = {};
    float acc3[2][4][4] = {};

    // ldmatrix per-lane offsets (loop-invariant)
    // A (m16 x k16): lanes 0-15 -> rows m0w+ (lane&15), k bytes 0-15; lanes 16-31 -> +16B
    uint32_t aOff0 = (uint32_t)(warp_m * 32 + (lane & 15)) * STR_B + (lane >> 4) * 16;
    uint32_t aOff1 = aOff0 + 16 * STR_B;
    // B (n16 x k16 per ldsm4): m0:n0-7/k0-7, m1:n0-7/k8-15, m2:n8-15/k0-7, m3:n8-15/k8-15
    uint32_t bOff0 = (uint32_t)(warp_n * 32 + ((lane >> 4) << 3) + (lane & 7)) * STR_B + ((lane >> 3) & 1) * 16;
    uint32_t bOff1 = bOff0 + 16 * STR_B;

    const int lrow = lane >> 2;
    const int lcol = lane & 3;
    const int NT = D_DIM / BKT;      // 16

    for (int kt = 0; kt < NT; kt++) {
        const int cur = kt & 1;
        CP_WAIT1();
        __syncthreads();

        uint32_t aS  = base + cur * STAGE_U;
        uint32_t b1S = aS + A_TILE_B;
        uint32_t b3S = b1S + BU_TILE_B;

#pragma unroll
        for (int ks = 0; ks < BKT / 16; ks++) {  // 4 k16-steps, each 32B
            uint32_t a[2][4], b1[2][4], b3[2][4];
            ldsm4(a[0],  aS  + aOff0 + ks * 32);
            ldsm4(a[1],  aS  + aOff1 + ks * 32);
            ldsm4(b1[0], b1S + bOff0 + ks * 32);
            ldsm4(b1[1], b1S + bOff1 + ks * 32);
            ldsm4(b3[0], b3S + bOff0 + ks * 32);
            ldsm4(b3[1], b3S + bOff1 + ks * 32);
#pragma unroll
            for (int mt = 0; mt < 2; mt++)
#pragma unroll
                for (int p = 0; p < 2; p++) {
                    mma16(acc1[mt][2 * p + 0], a[mt], &b1[p][0]);
                    mma16(acc1[mt][2 * p + 1], a[mt], &b1[p][2]);
                    mma16(acc3[mt][2 * p + 0], a[mt], &b3[p][0]);
                    mma16(acc3[mt][2 * p + 1], a[mt], &b3[p][2]);
                }
        }
        __syncthreads();
        if (kt + 2 < NT) load_tile(cur, (kt + 2) * BKT);
        else CP_COMMIT();
    }

    // epilogue: silu(u1)*u3 -> g_U (fp16)
#pragma unroll
    for (int mt = 0; mt < 2; mt++) {
#pragma unroll
        for (int half = 0; half < 2; half++) {
            int r = warp_m * 32 + mt * 16 + lrow + half * 8;
            if (m0 + r < count) {
                __half* urow = g_U + (size_t)sEnt[r] * H_DIM;
#pragma unroll
                for (int nt = 0; nt < 4; nt++) {
                    int cbase = n0 + warp_n * 32 + nt * 8 + 2 * lcol;
                    float z0 = acc1[mt][nt][half * 2 + 0];
                    float z1 = acc1[mt][nt][half * 2 + 1];
                    float u0 = z0 / (1.f + expf(-z0)) * acc3[mt][nt][half * 2 + 0];
                    float u1 = z1 / (1.f + expf(-z1)) * acc3[mt][nt][half * 2 + 1];
                    *(__half2*)(urow + cbase) = __floats2half2_rn(u0, u1);
                }
            }
        }
    }
}

// ============================================================
// DOWN: per expert, Y = gate * (U@W2). CTA: M=128, N=128, K=512.
// 8 warps 4(m)x2(n): warp tile 32m x 64n. fp16 m16n8k16.
// ============================================================
__global__ __launch_bounds__(256, 2) void down_gemm_kernel() {
    const int e = blockIdx.z;
    const int count = g_count[e];
    const int m0 = blockIdx.x * 128;
    if (m0 >= count) return;
    const int n0 = blockIdx.y * 128;

    extern __shared__ __align__(128) char smem[];
    __shared__ int   sEnt[128];
    __shared__ float sGate[128];

    const int tid = threadIdx.x;
    const int wid = tid >> 5, lane = tid & 31;
    const int warp_m = wid >> 1, warp_n = wid & 1;

    uint32_t base = smem_u32(smem);

    if (tid < 128) {
        int p = m0 + tid;
        sEnt[tid]  = (p < count) ? g_entry[e][p] : g_entry[e][0];
        sGate[tid] = (p < count) ? g_gateW[e][p] : 0.f;
    }
    __syncthreads();

    const __half* W2 = g_w2t + (size_t)e * D_DIM * H_DIM;   // [d][h]

    auto load_tile = [&](int buf, int k0) {
        uint32_t aB = base + buf * STAGE_D;
        uint32_t bB = aB + A_TILE_B;
#pragma unroll
        for (int i = 0; i < 4; i++) {            // A: 128 rows x 8 chunks
            int c = tid + i * 256, row = c >> 3, q = c & 7;
            cp16(aB + row * STR_B + q * 16,
                 g_U + (size_t)sEnt[row] * H_DIM + k0 + q * 8);
        }
#pragma unroll
        for (int i = 0; i < 4; i++) {            // B: 128 n-rows x 8 chunks
            int c = tid + i * 256, row = c >> 3, q = c & 7;
            cp16(bB + row * STR_B + q * 16,
                 W2 + (size_t)(n0 + row) * H_DIM + k0 + q * 8);
        }
        CP_COMMIT();
    };

    load_tile(0, 0);
    load_tile(1, BKT);

    float acc[2][8][4] = {};

    uint32_t aOff0 = (uint32_t)(warp_m * 32 + (lane & 15)) * STR_B + (lane >> 4) * 16;
    uint32_t aOff1 = aOff0 + 16 * STR_B;
    uint32_t bOffBase = (uint32_t)(warp_n * 64 + ((lane >> 4) << 3) + (lane & 7)) * STR_B + ((lane >> 3) & 1) * 16;

    const int lrow = lane >> 2;
    const int lcol = lane & 3;
    const int NT = H_DIM / BKT;   // 8

    for (int kt = 0; kt < NT; kt++) {
        const int cur = kt & 1;
        CP_WAIT1();
        __syncthreads();

        uint32_t aS = base + cur * STAGE_D;
        uint32_t bS = aS + A_TILE_B;

#pragma unroll
        for (int ks = 0; ks < BKT / 16; ks++) {
            uint32_t a[2][4], b[4][4];
            ldsm4(a[0], aS + aOff0 + ks * 32);
            ldsm4(a[1], aS + aOff1 + ks * 32);
#pragma unroll
            for (int p = 0; p < 4; p++)
                ldsm4(b[p], bS + bOffBase + p * (16 * STR_B) + ks * 32);
#pragma unroll
            for (int mt = 0; mt < 2; mt++)
#pragma unroll
                for (int p = 0; p < 4; p++) {
                    mma16(acc[mt][2 * p + 0], a[mt], &b[p][0]);
                    mma16(acc[mt][2 * p + 1], a[mt], &b[p][2]);
                }
        }
        __syncthreads();
        if (kt + 2 < NT) load_tile(cur, (kt + 2) * BKT);
        else CP_COMMIT();
    }

#pragma unroll
    for (int mt = 0; mt < 2; mt++) {
#pragma unroll
        for (int half = 0; half < 2; half++) {
            int r = warp_m * 32 + mt * 16 + lrow + half * 8;
            if (m0 + r < count) {
                float g = sGate[r];
                float* yrow = g_Y + (size_t)sEnt[r] * D_DIM;
#pragma unroll
                for (int nt = 0; nt < 8; nt++) {
                    int cbase = n0 + warp_n * 64 + nt * 8 + 2 * lcol;
                    float2 o;
                    o.x = g * acc[mt][nt][half * 2 + 0];
                    o.y = g * acc[mt][nt][half * 2 + 1];
                    *(float2*)(yrow + cbase) = o;
                }
            }
        }
    }
}

// ---------------- kernel: combine two slots per token ----------------
__global__ void combine_kernel(float* __restrict__ out) {
    size_t idx4 = (size_t)blockIdx.x * blockDim.x + threadIdx.x;
    size_t total4 = (size_t)T_TOK * D_DIM / 4;
    if (idx4 >= total4) return;
    size_t bofs = idx4 * 4;
    size_t t = bofs >> 10;
    size_t d = bofs & (D_DIM - 1);
    float4 a = *(const float4*)(g_Y + ((size_t)(2 * t) * D_DIM + d));
    float4 b = *(const float4*)(g_Y + ((size_t)(2 * t + 1) * D_DIM + d));
    float4 r;
    r.x = a.x + b.x; r.y = a.y + b.y; r.z = a.z + b.z; r.w = a.w + b.w;
    *(float4*)(out + bofs) = r;
}

// ---------------- launch ----------------
extern "C" void kernel_launch(void* const* d_in, const int* in_sizes, int n_in,
                              void* d_out, int out_size) {
    const float* x  = (const float*)d_in[0];
    const float* wr = (const float*)d_in[1];
    const float* w1 = (const float*)d_in[2];
    const float* w2 = (const float*)d_in[3];
    const float* w3 = (const float*)d_in[4];
    float* out = (float*)d_out;

    cudaFuncSetAttribute(up_gemm_kernel,   cudaFuncAttributeMaxDynamicSharedMemorySize, UP_SMEM);
    cudaFuncSetAttribute(down_gemm_kernel, cudaFuncAttributeMaxDynamicSharedMemorySize, DOWN_SMEM);

    zero_counts_kernel<<<1, 32>>>();
    router_kernel<<<T_TOK / 8, 256>>>(x, wr);

    {   // w1 [e][1024][512] -> g_w1t [e][512][1024] half; same for w3; w2 [e][512][1024] -> g_w2t [e][1024][512]
        dim3 b(32, 8);
        dim3 g13(512 / 32, 1024 / 32, E_NUM);
        transpose_w_kernel<<<g13, b>>>(w1, 0, 1024, 512);
        transpose_w_kernel<<<g13, b>>>(w3, 1, 1024, 512);
        dim3 g2(1024 / 32, 512 / 32, E_NUM);
        transpose_w_kernel<<<g2, b>>>(w2, 2, 512, 1024);
    }

    {
        dim3 g(T_TOK / 128, H_DIM / 64, E_NUM);   // (64, 8, 8)
        up_gemm_kernel<<<g, 256, UP_SMEM>>>();
    }
    {
        dim3 g(T_TOK / 128, D_DIM / 128, E_NUM);  // (64, 8, 8)
        down_gemm_kernel<<<g, 256, DOWN_SMEM>>>();
    }

    size_t total4 = (size_t)T_TOK * D_DIM / 4;
    combine_kernel<<<(unsigned)((total4 + 255) / 256), 256>>>(out);
}

// round 9
// speedup vs baseline: 5.7235x; 1.0302x over previous
#include <cuda_runtime.h>
#include <cuda_fp16.h>
#include <cstdint>
#include <math.h>

// ---------------- problem constants ----------------
#define T_TOK 8192
#define D_DIM 1024
#define E_NUM 8
#define H_DIM 512
#define NSLOT (2 * T_TOK)

// ---------------- device scratch (referenced ONLY from device code) ------
__device__ int   g_count[E_NUM];
__device__ int   g_entry[E_NUM][T_TOK];
__device__ float g_gateW[E_NUM][T_TOK];
__device__ __align__(16) __half g_Xh[(size_t)T_TOK * D_DIM];           // fp16 x
__device__ __align__(16) __half g_w1h[(size_t)E_NUM * D_DIM * H_DIM];  // [e][d][h] fp16 (orig layout)
__device__ __align__(16) __half g_w3h[(size_t)E_NUM * D_DIM * H_DIM];  // [e][d][h]
__device__ __align__(16) __half g_w2h[(size_t)E_NUM * H_DIM * D_DIM];  // [e][h][d]
__device__ __align__(16) __half g_U[(size_t)NSLOT * H_DIM];            // SwiGLU hidden fp16
__device__ __align__(16) float  g_Y[(size_t)NSLOT * D_DIM];            // gated down-proj fp32

// ---------------- helpers (sm_80-level PTX only) ----
__device__ __forceinline__ uint32_t smem_u32(const void* p) {
    uint32_t a;
    asm("{ .reg .u64 t; cvta.to.shared.u64 t, %1; cvt.u32.u64 %0, t; }" : "=r"(a) : "l"(p));
    return a;
}
__device__ __forceinline__ void cp16(uint32_t dst, const void* src) {
    asm volatile("cp.async.cg.shared.global [%0], [%1], 16;" :: "r"(dst), "l"(src));
}
#define CP_COMMIT() asm volatile("cp.async.commit_group;" ::: "memory")
#define CP_WAIT1()  asm volatile("cp.async.wait_group 1;" ::: "memory")

// ldmatrix x4: four 8x8 b16 matrices
__device__ __forceinline__ void ldsm4(uint32_t* r, uint32_t addr) {
    asm volatile("ldmatrix.sync.aligned.m8n8.x4.shared.b16 {%0,%1,%2,%3}, [%4];"
        : "=r"(r[0]), "=r"(r[1]), "=r"(r[2]), "=r"(r[3]) : "r"(addr));
}
// transposing variant: rows are k-rows of [k][n] tiles -> col-major B fragments
__device__ __forceinline__ void ldsm4t(uint32_t* r, uint32_t addr) {
    asm volatile("ldmatrix.sync.aligned.m8n8.x4.trans.shared.b16 {%0,%1,%2,%3}, [%4];"
        : "=r"(r[0]), "=r"(r[1]), "=r"(r[2]), "=r"(r[3]) : "r"(addr));
}

// mma.sync m16n8k16 fp16 -> fp32: D = A*B + D
__device__ __forceinline__ void mma16(float* c, const uint32_t* a, const uint32_t* b) {
    asm volatile(
        "mma.sync.aligned.m16n8k16.row.col.f32.f16.f16.f32 "
        "{%0,%1,%2,%3}, {%4,%5,%6,%7}, {%8,%9}, {%0,%1,%2,%3};"
        : "+f"(c[0]), "+f"(c[1]), "+f"(c[2]), "+f"(c[3])
        : "r"(a[0]), "r"(a[1]), "r"(a[2]), "r"(a[3]), "r"(b[0]), "r"(b[1]));
}

// ---------------- kernel: zero counters ----------------
__global__ void zero_counts_kernel() {
    if (threadIdx.x < E_NUM) g_count[threadIdx.x] = 0;
}

// ---------------- kernel: router + fused fp16 convert of x ----------------
__global__ void router_kernel(const float* __restrict__ x, const float* __restrict__ wr) {
    __shared__ float sWr[D_DIM * E_NUM];
    for (int i = threadIdx.x; i < D_DIM * E_NUM; i += blockDim.x) sWr[i] = wr[i];
    __syncthreads();

    int warp = threadIdx.x >> 5, lane = threadIdx.x & 31;
    int t = blockIdx.x * 8 + warp;
    if (t >= T_TOK) return;

    float acc[E_NUM];
#pragma unroll
    for (int e = 0; e < E_NUM; e++) acc[e] = 0.f;
    const float* xr = x + (size_t)t * D_DIM;
    __half* xo = g_Xh + (size_t)t * D_DIM;
    for (int d = lane; d < D_DIM; d += 32) {
        float xv = xr[d];
        xo[d] = __float2half_rn(xv);
#pragma unroll
        for (int e = 0; e < E_NUM; e++) acc[e] = fmaf(xv, sWr[d * E_NUM + e], acc[e]);
    }
#pragma unroll
    for (int off = 16; off > 0; off >>= 1)
#pragma unroll
        for (int e = 0; e < E_NUM; e++) acc[e] += __shfl_down_sync(0xffffffffu, acc[e], off);

    if (lane == 0) {
        float m = acc[0];
#pragma unroll
        for (int e = 1; e < E_NUM; e++) m = fmaxf(m, acc[e]);
        float p[E_NUM], s = 0.f;
#pragma unroll
        for (int e = 0; e < E_NUM; e++) { p[e] = expf(acc[e] - m); s += p[e]; }
        float inv = 1.f / s;
#pragma unroll
        for (int e = 0; e < E_NUM; e++) p[e] *= inv;

        int e0 = 0;
#pragma unroll
        for (int e = 1; e < E_NUM; e++) if (p[e] > p[e0]) e0 = e;
        int e1 = (e0 == 0) ? 1 : 0;
#pragma unroll
        for (int e = 0; e < E_NUM; e++) {
            if (e == e0) continue;
            if (p[e] > p[e1]) e1 = e;
        }
        int pos0 = atomicAdd(&g_count[e0], 1);
        g_entry[e0][pos0] = t * 2 + 0;
        g_gateW[e0][pos0] = p[e0];
        int pos1 = atomicAdd(&g_count[e1], 1);
        g_entry[e1][pos1] = t * 2 + 1;
        g_gateW[e1][pos1] = p[e1];
    }
}

// ---------------- kernel: fp16 convert weights (no transpose) ------------
__global__ void convert_w_kernel(const float* __restrict__ w1,
                                 const float* __restrict__ w2,
                                 const float* __restrict__ w3) {
    size_t i4 = (size_t)blockIdx.x * blockDim.x + threadIdx.x;
    size_t n4 = (size_t)E_NUM * D_DIM * H_DIM / 4;
    if (i4 >= n4) return;
    {
        float4 v = *(const float4*)(w1 + i4 * 4);
        __half2 h0 = __floats2half2_rn(v.x, v.y), h1 = __floats2half2_rn(v.z, v.w);
        *(uint2*)(g_w1h + i4 * 4) = make_uint2(*(uint32_t*)&h0, *(uint32_t*)&h1);
    }
    {
        float4 v = *(const float4*)(w3 + i4 * 4);
        __half2 h0 = __floats2half2_rn(v.x, v.y), h1 = __floats2half2_rn(v.z, v.w);
        *(uint2*)(g_w3h + i4 * 4) = make_uint2(*(uint32_t*)&h0, *(uint32_t*)&h1);
    }
    {
        float4 v = *(const float4*)(w2 + i4 * 4);
        __half2 h0 = __floats2half2_rn(v.x, v.y), h1 = __floats2half2_rn(v.z, v.w);
        *(uint2*)(g_w2h + i4 * 4) = make_uint2(*(uint32_t*)&h0, *(uint32_t*)&h1);
    }
}

// ---------------- GEMM tiling constants ----------------
#define BKT 64                          // K per smem tile (halves)
#define ASTR 144                        // A smem row stride bytes (128 data + 16 pad)
#define BUSTR 144                       // up B k-row stride (64 n-halves = 128B + pad)
#define BDSTR 272                       // down B k-row stride (128 n-halves = 256B + pad)
#define A_TILE_B (128 * ASTR)           // 18432
#define BU_TILE_B (BKT * BUSTR)         // 9216 (per weight)
#define BD_TILE_B (BKT * BDSTR)         // 17408
#define STAGE_U (A_TILE_B + 2 * BU_TILE_B)  // 36864
#define STAGE_D (A_TILE_B + BD_TILE_B)      // 35840
#define UP_SMEM   (2 * STAGE_U)             // 73728
#define DOWN_SMEM (2 * STAGE_D)             // 71680

// ============================================================
// UP: per expert, U = silu(Xg@W1)*(Xg@W3). CTA: M=128, N=64 (each), K=1024.
// A [m][k] via ldsm4; B direct from [k][n] via ldsm4t. 2-stage ring.
// ============================================================
__global__ __launch_bounds__(256, 2) void up_gemm_kernel() {
    const int e = blockIdx.z;
    const int count = g_count[e];
    const int m0 = blockIdx.x * 128;
    if (m0 >= count) return;
    const int n0 = blockIdx.y * 64;

    extern __shared__ __align__(128) char smem[];
    __shared__ int sTok[128];
    __shared__ int sEnt[128];

    const int tid = threadIdx.x;
    const int wid = tid >> 5, lane = tid & 31;
    const int warp_m = wid >> 1, warp_n = wid & 1;

    uint32_t base = smem_u32(smem);

    if (tid < 128) {
        int p = m0 + tid;
        int ent = (p < count) ? g_entry[e][p] : g_entry[e][0];
        sEnt[tid] = ent;
        sTok[tid] = ent >> 1;
    }
    __syncthreads();

    const __half* W1 = g_w1h + (size_t)e * D_DIM * H_DIM;   // [d][h] = [k][n]
    const __half* W3 = g_w3h + (size_t)e * D_DIM * H_DIM;

    auto load_tile = [&](int buf, int k0) {      // k0 in halves
        uint32_t aB  = base + buf * STAGE_U;
        uint32_t b1B = aB + A_TILE_B;
        uint32_t b3B = b1B + BU_TILE_B;
#pragma unroll
        for (int i = 0; i < 4; i++) {            // A: 128 m-rows x 8 chunks
            int c = tid + i * 256, row = c >> 3, q = c & 7;
            cp16(aB + row * ASTR + q * 16,
                 g_Xh + (size_t)sTok[row] * D_DIM + k0 + q * 8);
        }
#pragma unroll
        for (int i = 0; i < 2; i++) {            // B1: 64 k-rows x 8 chunks (n-slice 64)
            int c = tid + i * 256, row = c >> 3, q = c & 7;
            cp16(b1B + row * BUSTR + q * 16,
                 W1 + (size_t)(k0 + row) * H_DIM + n0 + q * 8);
        }
#pragma unroll
        for (int i = 0; i < 2; i++) {            // B3
            int c = tid + i * 256, row = c >> 3, q = c & 7;
            cp16(b3B + row * BUSTR + q * 16,
                 W3 + (size_t)(k0 + row) * H_DIM + n0 + q * 8);
        }
        CP_COMMIT();
    };

    load_tile(0, 0);
    load_tile(1, BKT);

    float acc1[2][4][4] = {};
    float acc3[2][4][4] = {};

    // A ldmatrix offsets (non-trans, [m][k])
    uint32_t aOff0 = (uint32_t)(warp_m * 32 + (lane & 15)) * ASTR + (lane >> 4) * 16;
    uint32_t aOff1 = aOff0 + 16 * ASTR;
    // B trans-ldmatrix offsets ([k][n]): lanes 0-7 -> k0-7, 8-15 -> k8-15 (b1-half),
    // 16-23 -> n+8 k0-7, 24-31 -> n+8 k8-15
    uint32_t bOffT = (uint32_t)((lane & 7) + ((lane >> 3) & 1) * 8) * BUSTR
                   + (uint32_t)(warp_n * 32 + ((lane >> 4) & 1) * 8) * 2;

    const int lrow = lane >> 2;
    const int lcol = lane & 3;
    const int NT = D_DIM / BKT;      // 16

    for (int kt = 0; kt < NT; kt++) {
        const int cur = kt & 1;
        CP_WAIT1();
        __syncthreads();

        uint32_t aS  = base + cur * STAGE_U;
        uint32_t b1S = aS + A_TILE_B;
        uint32_t b3S = b1S + BU_TILE_B;

#pragma unroll
        for (int ks = 0; ks < BKT / 16; ks++) {  // 4 k16-steps
            uint32_t a[2][4], b1[2][4], b3[2][4];
            ldsm4(a[0], aS + aOff0 + ks * 32);
            ldsm4(a[1], aS + aOff1 + ks * 32);
#pragma unroll
            for (int p = 0; p < 2; p++) {        // p: n16 step (+32B in n)
                ldsm4t(b1[p], b1S + bOffT + p * 32 + ks * (16 * BUSTR));
                ldsm4t(b3[p], b3S + bOffT + p * 32 + ks * (16 * BUSTR));
            }
#pragma unroll
            for (int mt = 0; mt < 2; mt++)
#pragma unroll
                for (int p = 0; p < 2; p++) {
                    mma16(acc1[mt][2 * p + 0], a[mt], &b1[p][0]);
                    mma16(acc1[mt][2 * p + 1], a[mt], &b1[p][2]);
                    mma16(acc3[mt][2 * p + 0], a[mt], &b3[p][0]);
                    mma16(acc3[mt][2 * p + 1], a[mt], &b3[p][2]);
                }
        }
        __syncthreads();
        if (kt + 2 < NT) load_tile(cur, (kt + 2) * BKT);
        else CP_COMMIT();
    }

    // epilogue: silu(u1)*u3 -> g_U (fp16)
#pragma unroll
    for (int mt = 0; mt < 2; mt++) {
#pragma unroll
        for (int half = 0; half < 2; half++) {
            int r = warp_m * 32 + mt * 16 + lrow + half * 8;
            if (m0 + r < count) {
                __half* urow = g_U + (size_t)sEnt[r] * H_DIM;
#pragma unroll
                for (int nt = 0; nt < 4; nt++) {
                    int cbase = n0 + warp_n * 32 + nt * 8 + 2 * lcol;
                    float z0 = acc1[mt][nt][half * 2 + 0];
                    float z1 = acc1[mt][nt][half * 2 + 1];
                    float u0 = z0 / (1.f + expf(-z0)) * acc3[mt][nt][half * 2 + 0];
                    float u1 = z1 / (1.f + expf(-z1)) * acc3[mt][nt][half * 2 + 1];
                    *(__half2*)(urow + cbase) = __floats2half2_rn(u0, u1);
                }
            }
        }
    }
}

// ============================================================
// DOWN: per expert, Y = gate * (U@W2). CTA: M=128, N=128, K=512.
// A = U [m][k]; B direct from w2 [k][n] via ldsm4t. 2-stage ring.
// ============================================================
__global__ __launch_bounds__(256, 2) void down_gemm_kernel() {
    const int e = blockIdx.z;
    const int count = g_count[e];
    const int m0 = blockIdx.x * 128;
    if (m0 >= count) return;
    const int n0 = blockIdx.y * 128;

    extern __shared__ __align__(128) char smem[];
    __shared__ int   sEnt[128];
    __shared__ float sGate[128];

    const int tid = threadIdx.x;
    const int wid = tid >> 5, lane = tid & 31;
    const int warp_m = wid >> 1, warp_n = wid & 1;

    uint32_t base = smem_u32(smem);

    if (tid < 128) {
        int p = m0 + tid;
        sEnt[tid]  = (p < count) ? g_entry[e][p] : g_entry[e][0];
        sGate[tid] = (p < count) ? g_gateW[e][p] : 0.f;
    }
    __syncthreads();

    const __half* W2 = g_w2h + (size_t)e * H_DIM * D_DIM;   // [h][d] = [k][n]

    auto load_tile = [&](int buf, int k0) {
        uint32_t aB = base + buf * STAGE_D;
        uint32_t bB = aB + A_TILE_B;
#pragma unroll
        for (int i = 0; i < 4; i++) {            // A: 128 m-rows x 8 chunks
            int c = tid + i * 256, row = c >> 3, q = c & 7;
            cp16(aB + row * ASTR + q * 16,
                 g_U + (size_t)sEnt[row] * H_DIM + k0 + q * 8);
        }
#pragma unroll
        for (int i = 0; i < 4; i++) {            // B: 64 k-rows x 16 chunks (n-slice 128)
            int c = tid + i * 256, row = c >> 4, q = c & 15;
            cp16(bB + row * BDSTR + q * 16,
                 W2 + (size_t)(k0 + row) * D_DIM + n0 + q * 8);
        }
        CP_COMMIT();
    };

    load_tile(0, 0);
    load_tile(1, BKT);

    float acc[2][8][4] = {};

    uint32_t aOff0 = (uint32_t)(warp_m * 32 + (lane & 15)) * ASTR + (lane >> 4) * 16;
    uint32_t aOff1 = aOff0 + 16 * ASTR;
    uint32_t bOffT = (uint32_t)((lane & 7) + ((lane >> 3) & 1) * 8) * BDSTR
                   + (uint32_t)(warp_n * 64 + ((lane >> 4) & 1) * 8) * 2;

    const int lrow = lane >> 2;
    const int lcol = lane & 3;
    const int NT = H_DIM / BKT;   // 8

    for (int kt = 0; kt < NT; kt++) {
        const int cur = kt & 1;
        CP_WAIT1();
        __syncthreads();

        uint32_t aS = base + cur * STAGE_D;
        uint32_t bS = aS + A_TILE_B;

#pragma unroll
        for (int ks = 0; ks < BKT / 16; ks++) {
            uint32_t a[2][4], b[4][4];
            ldsm4(a[0], aS + aOff0 + ks * 32);
            ldsm4(a[1], aS + aOff1 + ks * 32);
#pragma unroll
            for (int p = 0; p < 4; p++)          // p: n16 step (+32B)
                ldsm4t(b[p], bS + bOffT + p * 32 + ks * (16 * BDSTR));
#pragma unroll
            for (int mt = 0; mt < 2; mt++)
#pragma unroll
                for (int p = 0; p < 4; p++) {
                    mma16(acc[mt][2 * p + 0], a[mt], &b[p][0]);
                    mma16(acc[mt][2 * p + 1], a[mt], &b[p][2]);
                }
        }
        __syncthreads();
        if (kt + 2 < NT) load_tile(cur, (kt + 2) * BKT);
        else CP_COMMIT();
    }

#pragma unroll
    for (int mt = 0; mt < 2; mt++) {
#pragma unroll
        for (int half = 0; half < 2; half++) {
            int r = warp_m * 32 + mt * 16 + lrow + half * 8;
            if (m0 + r < count) {
                float g = sGate[r];
                float* yrow = g_Y + (size_t)sEnt[r] * D_DIM;
#pragma unroll
                for (int nt = 0; nt < 8; nt++) {
                    int cbase = n0 + warp_n * 64 + nt * 8 + 2 * lcol;
                    float2 o;
                    o.x = g * acc[mt][nt][half * 2 + 0];
                    o.y = g * acc[mt][nt][half * 2 + 1];
                    *(float2*)(yrow + cbase) = o;
                }
            }
        }
    }
}

// ---------------- kernel: combine two slots per token ----------------
__global__ void combine_kernel(float* __restrict__ out) {
    size_t idx4 = (size_t)blockIdx.x * blockDim.x + threadIdx.x;
    size_t total4 = (size_t)T_TOK * D_DIM / 4;
    if (idx4 >= total4) return;
    size_t bofs = idx4 * 4;
    size_t t = bofs >> 10;
    size_t d = bofs & (D_DIM - 1);
    float4 a = *(const float4*)(g_Y + ((size_t)(2 * t) * D_DIM + d));
    float4 b = *(const float4*)(g_Y + ((size_t)(2 * t + 1) * D_DIM + d));
    float4 r;
    r.x = a.x + b.x; r.y = a.y + b.y; r.z = a.z + b.z; r.w = a.w + b.w;
    *(float4*)(out + bofs) = r;
}

// ---------------- launch ----------------
extern "C" void kernel_launch(void* const* d_in, const int* in_sizes, int n_in,
                              void* d_out, int out_size) {
    const float* x  = (const float*)d_in[0];
    const float* wr = (const float*)d_in[1];
    const float* w1 = (const float*)d_in[2];
    const float* w2 = (const float*)d_in[3];
    const float* w3 = (const float*)d_in[4];
    float* out = (float*)d_out;

    cudaFuncSetAttribute(up_gemm_kernel,   cudaFuncAttributeMaxDynamicSharedMemorySize, UP_SMEM);
    cudaFuncSetAttribute(down_gemm_kernel, cudaFuncAttributeMaxDynamicSharedMemorySize, DOWN_SMEM);

    zero_counts_kernel<<<1, 32>>>();
    router_kernel<<<T_TOK / 8, 256>>>(x, wr);

    {
        int n4 = E_NUM * D_DIM * H_DIM / 4;   // 1M float4 per tensor
        convert_w_kernel<<<(n4 + 255) / 256, 256>>>(w1, w2, w3);
    }

    {
        dim3 g(T_TOK / 128, H_DIM / 64, E_NUM);   // (64, 8, 8)
        up_gemm_kernel<<<g, 256, UP_SMEM>>>();
    }
    {
        dim3 g(T_TOK / 128, D_DIM / 128, E_NUM);  // (64, 8, 8)
        down_gemm_kernel<<<g, 256, DOWN_SMEM>>>();
    }

    size_t total4 = (size_t)T_TOK * D_DIM / 4;
    combine_kernel<<<(unsigned)((total4 + 255) / 256), 256>>>(out);
}